// round 7
// baseline (speedup 1.0000x reference)
#include <cuda_runtime.h>
#include <cuda_fp16.h>
#include <cstdint>
#include <math.h>

// ---------------- problem constants ----------------
#define DIMC   256
#define SPAT   4096
#define NHEAD  8
#define HDIM   32
#define HIDM   53
#define MAXB   16

// ---------------- device scratch ----------------
__device__ float g_mean[MAXB * DIMC];
__device__ float g_bb[MAXB * 512];                         // adjusted bias [fc1;fcv]
__device__ float g_pool[MAXB * DIMC * 256];                // 16x16 pooled x (avg 4x4)
__device__ __half g_w1hi[512 * DIMC], g_w1lo[512 * DIMC];  // [fc1;fcv] fp16 split
__device__ __half g_xthi[(size_t)MAXB * SPAT * DIMC];      // X^T [b][s][k] fp16 split
__device__ __half g_xtlo[(size_t)MAXB * SPAT * DIMC];
__device__ __half g_pthi[MAXB * 256 * DIMC];               // pooled^T [b][p][k]
__device__ __half g_ptlo[MAXB * 256 * DIMC];
__device__ float g_pxv[MAXB * 512 * 256];                  // pooled fc1+fcv out
__device__ float g_cns[512 * 128];                         // normalized centers
__device__ float g_vcs[512 * 128];                         // value centers
__device__ float g_sim[(size_t)MAXB * 32 * 1024];          // per-(b,h,win) token sim
__device__ unsigned char g_mstar[(size_t)MAXB * 32 * 1024];
__device__ float g_outm[512 * 128];                        // cluster features
__device__ float g_y[512 * 1024];                          // W2 . outm

// ---------------- PTX helpers ----------------
__device__ __forceinline__ uint32_t smem_u32(const void* p) {
    uint32_t a;
    asm("{ .reg .u64 t; cvta.to.shared.u64 t, %1; cvt.u32.u64 %0, t; }" : "=r"(a) : "l"(p));
    return a;
}
__device__ __forceinline__ void cp_async16(uint32_t s, const void* g) {
    asm volatile("cp.async.cg.shared.global [%0], [%1], 16;" :: "r"(s), "l"(g));
}
#define CP_COMMIT() asm volatile("cp.async.commit_group;" ::: "memory")
#define CP_WAIT(n)  asm volatile("cp.async.wait_group %0;" :: "n"(n) : "memory")

__device__ __forceinline__ void ldsm4(uint32_t* r, uint32_t a) {
    asm volatile("ldmatrix.sync.aligned.m8n8.x4.shared.b16 {%0,%1,%2,%3}, [%4];"
        : "=r"(r[0]), "=r"(r[1]), "=r"(r[2]), "=r"(r[3]) : "r"(a));
}
__device__ __forceinline__ void mma_f16(float* d, const uint32_t* a, const uint32_t* b) {
    asm volatile("mma.sync.aligned.m16n8k16.row.col.f32.f16.f16.f32 "
        "{%0,%1,%2,%3}, {%4,%5,%6,%7}, {%8,%9}, {%0,%1,%2,%3};"
        : "+f"(d[0]), "+f"(d[1]), "+f"(d[2]), "+f"(d[3])
        : "r"(a[0]), "r"(a[1]), "r"(a[2]), "r"(a[3]), "r"(b[0]), "r"(b[1]));
}
__device__ __forceinline__ void hsplit(float v, __half& h, __half& l) {
    h = __float2half_rn(v);
    l = __float2half_rn(v - __half2float(h));
}
// smem tile: 128 rows x 32 f16 (64B/row), 16B-chunk XOR swizzle
__device__ __forceinline__ uint32_t sw_off(int row, int chunk) {
    return (uint32_t)(row * 64 + ((chunk ^ ((row >> 1) & 3)) << 4));
}

// ---------------- kernel 1: 4x4 avg-pool (16x16) + spatial mean ----------------
__global__ __launch_bounds__(256)
void pool_kernel(const float* __restrict__ x) {
    int bc = blockIdx.x;                        // B*256
    const float* p = x + (size_t)bc * SPAT;
    __shared__ float sm[4096];
    __shared__ float red[256];
    int tid = threadIdx.x;
    for (int i = tid; i < 4096; i += 256) sm[i] = p[i];
    __syncthreads();
    int pi = tid >> 4, pj = tid & 15;
    float s = 0.f;
#pragma unroll
    for (int u = 0; u < 4; u++)
#pragma unroll
        for (int v = 0; v < 4; v++)
            s += sm[(pi * 4 + u) * 64 + pj * 4 + v];
    g_pool[(size_t)bc * 256 + tid] = s * (1.f / 16.f);
    red[tid] = s;
    __syncthreads();
    for (int off = 128; off > 0; off >>= 1) {
        if (tid < off) red[tid] += red[tid + off];
        __syncthreads();
    }
    if (tid == 0) g_mean[bc] = red[0] * (1.f / (float)SPAT);
}

// ---------------- kernel 2: adjusted bias ----------------
__global__ void bias_kernel(const float* __restrict__ w1, const float* __restrict__ b1,
                            const float* __restrict__ wv, const float* __restrict__ bv,
                            const float* __restrict__ scaler, int B) {
    int id = blockIdx.x * blockDim.x + threadIdx.x;
    if (id >= B * 512) return;
    int b = id >> 9, r = id & 511;
    const float* w = (r < 256) ? (w1 + (size_t)r * DIMC) : (wv + (size_t)(r - 256) * DIMC);
    float base = (r < 256) ? b1[r] : bv[r - 256];
    const float* mn = g_mean + b * DIMC;
    float s = 0.f;
#pragma unroll 8
    for (int c = 0; c < DIMC; c++) s += w[c] * scaler[c] * mn[c];
    g_bb[id] = base + s;
}

// ---------------- kernel 3: weight fp16 split ([fc1;fcv]) ----------------
__global__ void convw_kernel(const float* __restrict__ w1, const float* __restrict__ wv) {
    int i = blockIdx.x * blockDim.x + threadIdx.x;
    if (i < 65536) hsplit(w1[i], g_w1hi[i], g_w1lo[i]);
    else if (i < 131072) hsplit(wv[i - 65536], g_w1hi[i], g_w1lo[i]);
}

// ---------------- kernel 4: transpose+split [b][c][S] -> [b][s][c] hi/lo ----------------
__global__ void convx_kernel(const float* __restrict__ src, __half* __restrict__ dhi,
                             __half* __restrict__ dlo, int S) {
    __shared__ float t[32][33];
    int s0 = blockIdx.x * 32, c0 = blockIdx.y * 32, b = blockIdx.z;
    int tx = threadIdx.x, ty = threadIdx.y;
#pragma unroll
    for (int i = 0; i < 4; i++)
        t[ty + i * 8][tx] = src[((size_t)(b * DIMC + c0 + ty + i * 8)) * S + s0 + tx];
    __syncthreads();
#pragma unroll
    for (int i = 0; i < 4; i++) {
        int s = s0 + ty + i * 8;
        float v = t[tx][ty + i * 8];
        __half h, l;
        hsplit(v, h, l);
        size_t o = ((size_t)b * S + s) * DIMC + c0 + tx;
        dhi[o] = h;
        dlo[o] = l;
    }
}

// ---------------- kernel 5: generic HMMA fp16-split GEMM (pooled conv) ----------------
__global__ __launch_bounds__(256)
void gemm_hmma_kernel(const __half* __restrict__ whi, const __half* __restrict__ wlo,
                      const __half* __restrict__ xhi, const __half* __restrict__ xlo,
                      const float* __restrict__ bias, float* __restrict__ O,
                      int M, int S, int biasPerBatch) {
    extern __shared__ __align__(1024) char sm[];
    const int tid = threadIdx.x, lane = tid & 31, warp = tid >> 5;
    const int b = blockIdx.z, n0 = blockIdx.x * 128, m0 = blockIdx.y * 128;
    const int wm = (warp >> 2) * 64, wn = (warp & 3) * 32;

    const __half* srcs[4] = {
        whi + (size_t)m0 * DIMC, wlo + (size_t)m0 * DIMC,
        xhi + ((size_t)b * S + n0) * DIMC, xlo + ((size_t)b * S + n0) * DIMC };
    const uint32_t smb = smem_u32(sm);

    float acc[4][4][4];
#pragma unroll
    for (int i = 0; i < 4; i++)
#pragma unroll
        for (int j = 0; j < 4; j++)
#pragma unroll
            for (int k = 0; k < 4; k++) acc[i][j][k] = 0.f;

    auto load_stage = [&](int stage, int kc) {
#pragma unroll
        for (int t = 0; t < 4; t++) {
#pragma unroll
            for (int i = 0; i < 2; i++) {
                int chunkid = tid + 256 * i;
                int row = chunkid >> 2, c = chunkid & 3;
                cp_async16(smb + stage * 32768 + t * 8192 + sw_off(row, c),
                           srcs[t] + (size_t)row * DIMC + kc * 32 + c * 8);
            }
        }
        CP_COMMIT();
    };
    const int rl = lane & 7, sel = lane >> 3;

    load_stage(0, 0);
    int stage = 0;
    for (int kc = 0; kc < 8; kc++) {
        if (kc + 1 < 8) { load_stage(stage ^ 1, kc + 1); CP_WAIT(1); }
        else            { CP_WAIT(0); }
        __syncthreads();
        const uint32_t base = smb + stage * 32768;
#pragma unroll
        for (int ks = 0; ks < 2; ks++) {
            uint32_t ahi[4][4], alo[4][4];
#pragma unroll
            for (int mt = 0; mt < 4; mt++) {
                int row = wm + mt * 16 + (sel & 1) * 8 + rl;
                int ch = ks * 2 + (sel >> 1);
                uint32_t o = sw_off(row, ch);
                ldsm4(ahi[mt], base + o);
                ldsm4(alo[mt], base + 8192 + o);
            }
            uint32_t bhi[4][2], blo[4][2];
#pragma unroll
            for (int p = 0; p < 2; p++) {
                int row = wn + p * 16 + (sel >> 1) * 8 + rl;
                int ch = ks * 2 + (sel & 1);
                uint32_t o = sw_off(row, ch);
                uint32_t r4[4];
                ldsm4(r4, base + 16384 + o);
                bhi[2 * p][0] = r4[0]; bhi[2 * p][1] = r4[1];
                bhi[2 * p + 1][0] = r4[2]; bhi[2 * p + 1][1] = r4[3];
                ldsm4(r4, base + 24576 + o);
                blo[2 * p][0] = r4[0]; blo[2 * p][1] = r4[1];
                blo[2 * p + 1][0] = r4[2]; blo[2 * p + 1][1] = r4[3];
            }
#pragma unroll
            for (int mt = 0; mt < 4; mt++)
#pragma unroll
                for (int nt = 0; nt < 4; nt++) {
                    mma_f16(acc[mt][nt], ahi[mt], bhi[nt]);
                    mma_f16(acc[mt][nt], ahi[mt], blo[nt]);
                    mma_f16(acc[mt][nt], alo[mt], bhi[nt]);
                }
        }
        __syncthreads();
        stage ^= 1;
    }
    const int g = lane >> 2, tig = lane & 3;
    const int bofs = biasPerBatch ? b * M : 0;
#pragma unroll
    for (int mt = 0; mt < 4; mt++) {
        int r0 = m0 + wm + mt * 16 + g;
        float b0v = bias[bofs + r0];
        float b1v = bias[bofs + r0 + 8];
        float* orow0 = O + ((size_t)b * M + r0) * S + n0;
        float* orow1 = orow0 + (size_t)8 * S;
#pragma unroll
        for (int nt = 0; nt < 4; nt++) {
            int col = wn + nt * 8 + 2 * tig;
            *reinterpret_cast<float2*>(orow0 + col) =
                make_float2(acc[mt][nt][0] + b0v, acc[mt][nt][1] + b0v);
            *reinterpret_cast<float2*>(orow1 + col) =
                make_float2(acc[mt][nt][2] + b1v, acc[mt][nt][3] + b1v);
        }
    }
}

// ---------------- kernel 6: centers (pooled pipeline -> cns, vcs) ----------------
__global__ __launch_bounds__(256)
void centers_kernel(const float* __restrict__ w1, const float* __restrict__ bb1,
                    const float* __restrict__ w2, const float* __restrict__ bb2) {
    const int tid = threadIdx.x;
    const int bbk = blockIdx.x;           // b*32 + h*4 + win
    const int b = bbk >> 5;
    const int h = (bbk >> 2) & 7;
    const int fi = (bbk >> 1) & 1;
    const int fj = bbk & 1;

    __shared__ float a8[2048];
    __shared__ float hbuf[HIDM * 64];
    __shared__ float w1s[HIDM * HDIM], b1s[HIDM], w2s[HDIM * HIDM], b2s[HDIM];
    __shared__ float ctrs[128], vcs[128], cavg[128];
    __shared__ float cnorm[4];

    for (int i = tid; i < HIDM * HDIM; i += 256) { w1s[i] = w1[i]; w2s[i] = w2[i]; }
    if (tid < HIDM) b1s[tid] = bb1[tid];
    if (tid < HDIM) b2s[tid] = bb2[tid];

    for (int pass = 0; pass < 2; pass++) {
        const int base_row = (pass == 0) ? (256 + h * HDIM) : (h * HDIM);
        float* dst = (pass == 0) ? vcs : ctrs;
        __syncthreads();
#pragma unroll
        for (int rep = 0; rep < 8; rep++) {
            int e = rep * 256 + tid;
            int c = e >> 6, pos = e & 63;
            a8[c * 64 + pos] = g_pxv[((size_t)(b * 512) + base_row + c) * 256
                                     + (fi * 8 + (pos >> 3)) * 16 + fj * 8 + (pos & 7)];
        }
        __syncthreads();
        if (tid < 128) {
            int m = tid >> 5, c = tid & 31, qi = m >> 1, qj = m & 1;
            float s = 0.f;
#pragma unroll
            for (int u = 0; u < 4; u++)
#pragma unroll
                for (int v2 = 0; v2 < 4; v2++)
                    s += a8[c * 64 + (qi * 4 + u) * 8 + qj * 4 + v2];
            cavg[tid] = s * (1.f / 16.f);
        }
        for (int eh = tid; eh < HIDM * 64; eh += 256) {
            int j = eh >> 6, p = eh & 63;
            float s = b1s[j];
#pragma unroll
            for (int c = 0; c < HDIM; c++) s += w1s[j * HDIM + c] * a8[c * 64 + p];
            hbuf[eh] = 0.5f * s * (1.f + erff(s * 0.70710678118654752440f));
        }
        __syncthreads();
        for (int eo = tid; eo < 2048; eo += 256) {
            int c = eo >> 6, p = eo & 63;
            float s = b2s[c];
#pragma unroll
            for (int j = 0; j < HIDM; j++) s += w2s[c * HIDM + j] * hbuf[j * 64 + p];
            a8[eo] = s;
        }
        __syncthreads();
        if (tid < 128) {
            int m = tid >> 5, c = tid & 31, qi = m >> 1, qj = m & 1;
            float mx = -INFINITY;
#pragma unroll
            for (int u = 0; u < 4; u++)
#pragma unroll
                for (int v2 = 0; v2 < 4; v2++)
                    mx = fmaxf(mx, a8[c * 64 + (qi * 4 + u) * 8 + qj * 4 + v2]);
            dst[tid] = cavg[tid] + mx;
        }
        __syncthreads();
    }

    if (tid < 4) {
        float s = 0.f;
#pragma unroll
        for (int c = 0; c < HDIM; c++) { float v = ctrs[tid * 32 + c]; s += v * v; }
        cnorm[tid] = fmaxf(sqrtf(s), 1e-12f);
    }
    __syncthreads();
    if (tid < 128) {
        g_cns[(size_t)bbk * 128 + tid] = ctrs[tid] / cnorm[tid >> 5];
        g_vcs[(size_t)bbk * 128 + tid] = vcs[tid];
    }
}

// ---------------- kernel 7: main fused GEMM (fc1 only) + sim/argmax epilogue ----------------
__global__ __launch_bounds__(256)
void gemm_sim_kernel(const __half* __restrict__ whi, const __half* __restrict__ wlo,
                     const __half* __restrict__ xhi, const __half* __restrict__ xlo,
                     const float* __restrict__ alphaP, const float* __restrict__ betaP) {
    extern __shared__ __align__(1024) char sm[];   // mainloop 64KB; epilogue 128x132 fp32
    __shared__ float cns_s[4][2][4][32];
    const int tid = threadIdx.x, lane = tid & 31, warp = tid >> 5;
    const int b = blockIdx.z, n0 = blockIdx.x * 128, m0 = blockIdx.y * 128;
    const int wm = (warp >> 2) * 64, wn = (warp & 3) * 32;

    const __half* srcs[4] = {
        whi + (size_t)m0 * DIMC, wlo + (size_t)m0 * DIMC,
        xhi + ((size_t)b * SPAT + n0) * DIMC, xlo + ((size_t)b * SPAT + n0) * DIMC };
    const uint32_t smb = smem_u32(sm);

    float acc[4][4][4];
#pragma unroll
    for (int i = 0; i < 4; i++)
#pragma unroll
        for (int j = 0; j < 4; j++)
#pragma unroll
            for (int k = 0; k < 4; k++) acc[i][j][k] = 0.f;

    auto load_stage = [&](int stage, int kc) {
#pragma unroll
        for (int t = 0; t < 4; t++) {
#pragma unroll
            for (int i = 0; i < 2; i++) {
                int chunkid = tid + 256 * i;
                int row = chunkid >> 2, c = chunkid & 3;
                cp_async16(smb + stage * 32768 + t * 8192 + sw_off(row, c),
                           srcs[t] + (size_t)row * DIMC + kc * 32 + c * 8);
            }
        }
        CP_COMMIT();
    };
    const int rl = lane & 7, sel = lane >> 3;

    load_stage(0, 0);
    int stage = 0;
    for (int kc = 0; kc < 8; kc++) {
        if (kc + 1 < 8) { load_stage(stage ^ 1, kc + 1); CP_WAIT(1); }
        else            { CP_WAIT(0); }
        __syncthreads();
        const uint32_t base = smb + stage * 32768;
#pragma unroll
        for (int ks = 0; ks < 2; ks++) {
            uint32_t ahi[4][4], alo[4][4];
#pragma unroll
            for (int mt = 0; mt < 4; mt++) {
                int row = wm + mt * 16 + (sel & 1) * 8 + rl;
                int ch = ks * 2 + (sel >> 1);
                uint32_t o = sw_off(row, ch);
                ldsm4(ahi[mt], base + o);
                ldsm4(alo[mt], base + 8192 + o);
            }
            uint32_t bhi[4][2], blo[4][2];
#pragma unroll
            for (int p = 0; p < 2; p++) {
                int row = wn + p * 16 + (sel >> 1) * 8 + rl;
                int ch = ks * 2 + (sel & 1);
                uint32_t o = sw_off(row, ch);
                uint32_t r4[4];
                ldsm4(r4, base + 16384 + o);
                bhi[2 * p][0] = r4[0]; bhi[2 * p][1] = r4[1];
                bhi[2 * p + 1][0] = r4[2]; bhi[2 * p + 1][1] = r4[3];
                ldsm4(r4, base + 24576 + o);
                blo[2 * p][0] = r4[0]; blo[2 * p][1] = r4[1];
                blo[2 * p + 1][0] = r4[2]; blo[2 * p + 1][1] = r4[3];
            }
#pragma unroll
            for (int mt = 0; mt < 4; mt++)
#pragma unroll
                for (int nt = 0; nt < 4; nt++) {
                    mma_f16(acc[mt][nt], ahi[mt], bhi[nt]);
                    mma_f16(acc[mt][nt], ahi[mt], blo[nt]);
                    mma_f16(acc[mt][nt], alo[mt], bhi[nt]);
                }
        }
        __syncthreads();
        stage ^= 1;
    }

    // ---- epilogue: x1 tile -> smem, then per-token norms + sims + argmax ----
    const int h0 = m0 >> 5;                 // first head of this CTA (0 or 4)
    const int fi = (n0 >= 2048) ? 1 : 0;
    float* epi = (float*)sm;                // [128 rows][132 stride]
    {
        const int g = lane >> 2, tig = lane & 3;
#pragma unroll
        for (int mt = 0; mt < 4; mt++) {
            int lr0 = wm + mt * 16 + g;
            float b0v = g_bb[b * 512 + m0 + lr0];
            float b1v = g_bb[b * 512 + m0 + lr0 + 8];
#pragma unroll
            for (int nt = 0; nt < 4; nt++) {
                int col = wn + nt * 8 + 2 * tig;
                epi[lr0 * 132 + col]           = acc[mt][nt][0] + b0v;
                epi[lr0 * 132 + col + 1]       = acc[mt][nt][1] + b0v;
                epi[(lr0 + 8) * 132 + col]     = acc[mt][nt][2] + b1v;
                epi[(lr0 + 8) * 132 + col + 1] = acc[mt][nt][3] + b1v;
            }
        }
    }
    // load centers for this CTA's 4 heads x 2 windows
    for (int i = tid; i < 1024; i += 256) {
        int hl = i >> 8, fjj = (i >> 7) & 1, m = (i >> 5) & 3, d = i & 31;
        int bbk = b * 32 + (h0 + hl) * 4 + fi * 2 + fjj;
        cns_s[hl][fjj][m][d] = g_cns[(size_t)bbk * 128 + m * 32 + d];
    }
    __syncthreads();

    const float alpha = alphaP[0], beta = betaP[0];
    const int hl = tid >> 6, tp = tid & 63;
#pragma unroll
    for (int rep = 0; rep < 2; rep++) {
        int tk = tp * 2 + rep;
        int s = n0 + tk;
        int hj = s & 63, fj = hj >> 5;
        int nw = ((s >> 6) & 31) * 32 + (hj & 31);
        float nrm = 0.f, dm[4] = {0.f, 0.f, 0.f, 0.f};
#pragma unroll
        for (int d = 0; d < 32; d++) {
            float v = epi[(hl * 32 + d) * 132 + tk];
            nrm += v * v;
#pragma unroll
            for (int m = 0; m < 4; m++) dm[m] += cns_s[hl][fj][m][d] * v;
        }
        float inv = 1.f / fmaxf(sqrtf(nrm), 1e-12f);
        float best = -1.f; int bm = 0;
#pragma unroll
        for (int m = 0; m < 4; m++) {
            float sg = 1.f / (1.f + expf(-(beta + alpha * dm[m] * inv)));
            if (sg > best) { best = sg; bm = m; }
        }
        size_t idx = ((size_t)(b * 8 + h0 + hl) * 4 + fi * 2 + fj) * 1024 + nw;
        g_sim[idx] = best;
        g_mstar[idx] = (unsigned char)bm;
    }
}

// ---------------- kernel 8: t-accumulation + outm (per (b,win)) ----------------
__global__ __launch_bounds__(256)
void taccum_kernel(const float* __restrict__ wv) {
    const int blk = blockIdx.x;           // b*4 + win
    const int b = blk >> 2, win = blk & 3;
    const int fi = win >> 1, fj = win & 1;
    const int tid = threadIdx.x, lane = tid & 31, h = tid >> 5;

    __shared__ float stage[32 * 256];     // 32KB; reused as ts after token loop
    __shared__ float sims[8][32];
    __shared__ unsigned char mss[8][32];

    float tacc[4][8];
#pragma unroll
    for (int m = 0; m < 4; m++)
#pragma unroll
        for (int j = 0; j < 8; j++) tacc[m][j] = 0.f;
    float sig[4] = {0.f, 0.f, 0.f, 0.f};
    float cntv[4] = {0.f, 0.f, 0.f, 0.f};

    for (int wi = 0; wi < 32; wi++) {
        int srow = (fi * 32 + wi) * 64 + fj * 32;
        {   // stage 32 tokens x 256 c (reconstruct fp32 = hi + lo)
            int hj = tid >> 3, c0 = (tid & 7) * 32;
            const __half2* ph = (const __half2*)(g_xthi + ((size_t)(b * SPAT) + srow + hj) * DIMC + c0);
            const __half2* pl = (const __half2*)(g_xtlo + ((size_t)(b * SPAT) + srow + hj) * DIMC + c0);
            float* st = stage + hj * 256 + c0;
#pragma unroll
            for (int j = 0; j < 16; j++) {
                float2 a = __half22float2(ph[j]);
                float2 l = __half22float2(pl[j]);
                st[2 * j] = a.x + l.x;
                st[2 * j + 1] = a.y + l.y;
            }
            size_t sb = ((size_t)(b * 8 + h) * 4 + win) * 1024 + wi * 32 + lane;
            sims[h][lane] = g_sim[sb];
            mss[h][lane] = g_mstar[sb];
        }
        __syncthreads();
        const float4* st4 = (const float4*)stage;
        for (int tk = 0; tk < 32; tk++) {
            float w = sims[h][tk];
            int m = mss[h][tk];
            float4 xa = st4[tk * 64 + lane * 2];
            float4 xb = st4[tk * 64 + lane * 2 + 1];
            float ws0 = (m == 0) ? w : 0.f, ws1 = (m == 1) ? w : 0.f;
            float ws2 = (m == 2) ? w : 0.f, ws3 = (m == 3) ? w : 0.f;
            float wsv[4] = {ws0, ws1, ws2, ws3};
#pragma unroll
            for (int mm = 0; mm < 4; mm++) {
                tacc[mm][0] += wsv[mm] * xa.x; tacc[mm][1] += wsv[mm] * xa.y;
                tacc[mm][2] += wsv[mm] * xa.z; tacc[mm][3] += wsv[mm] * xa.w;
                tacc[mm][4] += wsv[mm] * xb.x; tacc[mm][5] += wsv[mm] * xb.y;
                tacc[mm][6] += wsv[mm] * xb.z; tacc[mm][7] += wsv[mm] * xb.w;
            }
            sig[0] += ws0; sig[1] += ws1; sig[2] += ws2; sig[3] += ws3;
            cntv[0] += (m == 0) ? 1.f : 0.f; cntv[1] += (m == 1) ? 1.f : 0.f;
            cntv[2] += (m == 2) ? 1.f : 0.f; cntv[3] += (m == 3) ? 1.f : 0.f;
        }
        __syncthreads();
    }
    // ts[h][m][c] in smem (reuse stage)
    float* ts = stage;
#pragma unroll
    for (int mm = 0; mm < 4; mm++)
#pragma unroll
        for (int j = 0; j < 8; j++)
            ts[(h * 4 + mm) * 256 + lane * 8 + j] = tacc[mm][j];
    __syncthreads();
    // outm[h][m][d] = (Wv_row . t_m + sig_m*bbv_d + vcs)/(cnt_m+1)
    {
        int d = lane, row = h * 32 + d;
        const float* wrow = wv + (size_t)row * DIMC;
        float bbv = g_bb[b * 512 + 256 + row];
        int bbk = b * 32 + h * 4 + win;
#pragma unroll
        for (int mm = 0; mm < 4; mm++) {
            float s = 0.f;
            const float* tr = ts + (h * 4 + mm) * 256;
#pragma unroll 8
            for (int c = 0; c < DIMC; c++) s += wrow[c] * tr[c];
            float vc = g_vcs[(size_t)bbk * 128 + mm * 32 + d];
            g_outm[(size_t)bbk * 128 + mm * 32 + d] =
                (s + sig[mm] * bbv + vc) / (cntv[mm] + 1.f);
        }
    }
}

// ---------------- kernel 9: y = W2_hblock . outm ----------------
__global__ __launch_bounds__(256)
void y_kernel(const float* __restrict__ w2) {
    const int bbk = blockIdx.x;
    const int h = (bbk >> 2) & 7;
    const int tid = threadIdx.x;
    __shared__ float om[128];
    if (tid < 128) om[tid] = g_outm[(size_t)bbk * 128 + tid];
    __syncthreads();
    const float* wr = w2 + (size_t)tid * DIMC + h * HDIM;
    float wreg[32];
#pragma unroll
    for (int d = 0; d < HDIM; d++) wreg[d] = wr[d];
#pragma unroll
    for (int m = 0; m < 4; m++) {
        float s = 0.f;
#pragma unroll
        for (int d = 0; d < HDIM; d++) s += wreg[d] * om[m * 32 + d];
        g_y[(size_t)bbk * 1024 + m * 256 + tid] = s;
    }
}

// ---------------- kernel 10: combine -> final output ----------------
__global__ __launch_bounds__(256)
void combine_kernel(const float* __restrict__ b2, float* __restrict__ out) {
    const int o0 = blockIdx.x * 32;
    const int win = blockIdx.y;
    const int batch = blockIdx.z;
    const int fi = win >> 1, fj = win & 1;
    const int tid = threadIdx.x, lane = tid & 31, warp = tid >> 5;

    __shared__ float ys[8][4][33];
    __shared__ float b2s[32];

    for (int i = tid; i < 8 * 4 * 32; i += 256) {
        int h = i >> 7, m = (i >> 5) & 3, o = i & 31;
        ys[h][m][o] = g_y[((size_t)(batch * 8 + h) * 4 + win) * 1024 + m * 256 + o0 + o];
    }
    if (tid < 32) b2s[tid] = b2[o0 + tid];
    __syncthreads();

#pragma unroll
    for (int r = 0; r < 4; r++) {
        int wi = warp * 4 + r;
        int n = wi * 32 + lane;
        float simr[8];
        int mr[8];
#pragma unroll
        for (int h = 0; h < 8; h++) {
            size_t sb = ((size_t)(batch * 8 + h) * 4 + win) * 1024 + n;
            simr[h] = g_sim[sb];
            mr[h] = g_mstar[sb];
        }
        int s = (fi * 32 + wi) * 64 + fj * 32 + lane;
        float* op = out + ((size_t)batch * DIMC + o0) * SPAT + s;
#pragma unroll
        for (int o = 0; o < 32; o++) {
            float acc = b2s[o];
#pragma unroll
            for (int h = 0; h < 8; h++) acc += simr[h] * ys[h][mr[h]][o];
            op[(size_t)o * SPAT] = acc;
        }
    }
}

// ---------------- launcher ----------------
extern "C" void kernel_launch(void* const* d_in, const int* in_sizes, int n_in,
                              void* d_out, int out_size) {
    const float* x      = (const float*)d_in[0];
    const float* scaler = (const float*)d_in[1];
    const float* w_fc1  = (const float*)d_in[2];
    const float* b_fc1  = (const float*)d_in[3];
    const float* w_fcv  = (const float*)d_in[4];
    const float* b_fcv  = (const float*)d_in[5];
    const float* w_fc2  = (const float*)d_in[6];
    const float* b_fc2  = (const float*)d_in[7];
    const float* alpha  = (const float*)d_in[8];
    const float* beta   = (const float*)d_in[9];
    const float* off_w1 = (const float*)d_in[10];
    const float* off_b1 = (const float*)d_in[11];
    const float* off_w2 = (const float*)d_in[12];
    const float* off_b2 = (const float*)d_in[13];
    float* out = (float*)d_out;

    int B = in_sizes[0] / (DIMC * SPAT);
    if (B > MAXB) B = MAXB;

    float *p_pool, *p_bb, *p_pxv;
    __half *p_w1h, *p_w1l, *p_xth, *p_xtl, *p_pth, *p_ptl;
    cudaGetSymbolAddress((void**)&p_pool, g_pool);
    cudaGetSymbolAddress((void**)&p_bb,   g_bb);
    cudaGetSymbolAddress((void**)&p_pxv,  g_pxv);
    cudaGetSymbolAddress((void**)&p_w1h,  g_w1hi);
    cudaGetSymbolAddress((void**)&p_w1l,  g_w1lo);
    cudaGetSymbolAddress((void**)&p_xth,  g_xthi);
    cudaGetSymbolAddress((void**)&p_xtl,  g_xtlo);
    cudaGetSymbolAddress((void**)&p_pth,  g_pthi);
    cudaGetSymbolAddress((void**)&p_ptl,  g_ptlo);

    cudaFuncSetAttribute(gemm_hmma_kernel, cudaFuncAttributeMaxDynamicSharedMemorySize, 65536);
    cudaFuncSetAttribute(gemm_sim_kernel,  cudaFuncAttributeMaxDynamicSharedMemorySize, 67584);

    // 1. pooled x (16x16) + spatial mean, then adjusted biases
    pool_kernel<<<B * DIMC, 256>>>(x);
    bias_kernel<<<(B * 512 + 255) / 256, 256>>>(w_fc1, b_fc1, w_fcv, b_fcv, scaler, B);
    // 2. fp16 weight split, x transpose+split, pooled transpose+split
    convw_kernel<<<512, 256>>>(w_fc1, w_fcv);
    {
        dim3 g(SPAT / 32, DIMC / 32, B);
        convx_kernel<<<g, dim3(32, 8)>>>(x, p_xth, p_xtl, SPAT);
    }
    {
        dim3 g(256 / 32, DIMC / 32, B);
        convx_kernel<<<g, dim3(32, 8)>>>(p_pool, p_pth, p_ptl, 256);
    }
    // 3. pooled conv (fc1+fcv on pooled x)
    {
        dim3 grid(256 / 128, 512 / 128, B);
        gemm_hmma_kernel<<<grid, 256, 65536>>>(p_w1h, p_w1l, p_pth, p_ptl, p_bb, p_pxv, 512, 256, 1);
    }
    // 4. centers + normalized cn + value centers (tiny, pooled-only)
    centers_kernel<<<B * 32, 256>>>(off_w1, off_b1, off_w2, off_b2);
    // 5. main fused GEMM: fc1(x) + per-token norm/sim/argmax (no x1 materialization)
    {
        dim3 grid(SPAT / 128, 256 / 128, B);
        gemm_sim_kernel<<<grid, 256, 67584>>>(p_w1h, p_w1l, p_xth, p_xtl, alpha, beta);
    }
    // 6. t = sum sim*x per cluster, then outm = (Wv t + sig*bbv + vc)/(cnt+1)
    taccum_kernel<<<B * 4, 256>>>(w_fcv);
    // 7. y = W2 . outm per cluster
    y_kernel<<<B * 32, 256>>>(w_fc2);
    // 8. combine -> final output
    {
        dim3 grid(8, 4, B);
        combine_kernel<<<grid, 256>>>(b_fc2, out);
    }
}

// round 9
// speedup vs baseline: 1.7438x; 1.7438x over previous
#include <cuda_runtime.h>
#include <cuda_fp16.h>
#include <cstdint>
#include <math.h>

// ---------------- problem constants ----------------
#define DIMC   256
#define SPAT   4096
#define NHEAD  8
#define HDIM   32
#define HIDM   53
#define MAXB   16

// ---------------- device scratch ----------------
__device__ float g_mean[MAXB * DIMC];
__device__ float g_bb[MAXB * 512];                         // adjusted bias [fc1;fcv]
__device__ float g_pool[MAXB * DIMC * 256];                // 16x16 pooled x (avg 4x4)
__device__ __half g_w1hi[512 * DIMC], g_w1lo[512 * DIMC];  // [fc1;fcv] fp16 split
__device__ __half g_xthi[(size_t)MAXB * SPAT * DIMC];      // X^T [b][s][k] fp16 split
__device__ __half g_xtlo[(size_t)MAXB * SPAT * DIMC];
__device__ __half g_pthi[MAXB * 256 * DIMC];               // pooled^T [b][p][k]
__device__ __half g_ptlo[MAXB * 256 * DIMC];
__device__ float g_pxv[MAXB * 512 * 256];                  // pooled fc1+fcv out
__device__ float g_cns[512 * 128];                         // normalized centers
__device__ float g_vcs[512 * 128];                         // value centers
__device__ float g_sim[(size_t)MAXB * 32 * 1024];          // per-(b,h,win) token sim
__device__ unsigned char g_mstar[(size_t)MAXB * 32 * 1024];
__device__ float g_t[(size_t)MAXB * 4 * 8 * 4 * 256];      // [b][win][h][m][c]
__device__ float g_y[512 * 1024];                          // W2 . outm

// ---------------- PTX helpers ----------------
__device__ __forceinline__ uint32_t smem_u32(const void* p) {
    uint32_t a;
    asm("{ .reg .u64 t; cvta.to.shared.u64 t, %1; cvt.u32.u64 %0, t; }" : "=r"(a) : "l"(p));
    return a;
}
__device__ __forceinline__ void cp_async16(uint32_t s, const void* g) {
    asm volatile("cp.async.cg.shared.global [%0], [%1], 16;" :: "r"(s), "l"(g));
}
#define CP_COMMIT() asm volatile("cp.async.commit_group;" ::: "memory")
#define CP_WAIT(n)  asm volatile("cp.async.wait_group %0;" :: "n"(n) : "memory")

__device__ __forceinline__ void ldsm4(uint32_t* r, uint32_t a) {
    asm volatile("ldmatrix.sync.aligned.m8n8.x4.shared.b16 {%0,%1,%2,%3}, [%4];"
        : "=r"(r[0]), "=r"(r[1]), "=r"(r[2]), "=r"(r[3]) : "r"(a));
}
__device__ __forceinline__ void mma_f16(float* d, const uint32_t* a, const uint32_t* b) {
    asm volatile("mma.sync.aligned.m16n8k16.row.col.f32.f16.f16.f32 "
        "{%0,%1,%2,%3}, {%4,%5,%6,%7}, {%8,%9}, {%0,%1,%2,%3};"
        : "+f"(d[0]), "+f"(d[1]), "+f"(d[2]), "+f"(d[3])
        : "r"(a[0]), "r"(a[1]), "r"(a[2]), "r"(a[3]), "r"(b[0]), "r"(b[1]));
}
__device__ __forceinline__ void hsplit(float v, __half& h, __half& l) {
    h = __float2half_rn(v);
    l = __float2half_rn(v - __half2float(h));
}
// smem tile: 128 rows x 32 f16 (64B/row), 16B-chunk XOR swizzle
__device__ __forceinline__ uint32_t sw_off(int row, int chunk) {
    return (uint32_t)(row * 64 + ((chunk ^ ((row >> 1) & 3)) << 4));
}

// ---------------- kernel 1: 4x4 avg-pool (16x16) + spatial mean ----------------
__global__ __launch_bounds__(256)
void pool_kernel(const float* __restrict__ x) {
    int bc = blockIdx.x;                        // B*256
    const float* p = x + (size_t)bc * SPAT;
    __shared__ float sm[4096];
    __shared__ float red[256];
    int tid = threadIdx.x;
    for (int i = tid; i < 4096; i += 256) sm[i] = p[i];
    __syncthreads();
    int pi = tid >> 4, pj = tid & 15;
    float s = 0.f;
#pragma unroll
    for (int u = 0; u < 4; u++)
#pragma unroll
        for (int v = 0; v < 4; v++)
            s += sm[(pi * 4 + u) * 64 + pj * 4 + v];
    g_pool[(size_t)bc * 256 + tid] = s * (1.f / 16.f);
    red[tid] = s;
    __syncthreads();
    for (int off = 128; off > 0; off >>= 1) {
        if (tid < off) red[tid] += red[tid + off];
        __syncthreads();
    }
    if (tid == 0) g_mean[bc] = red[0] * (1.f / (float)SPAT);
}

// ---------------- kernel 2: adjusted bias ----------------
__global__ void bias_kernel(const float* __restrict__ w1, const float* __restrict__ b1,
                            const float* __restrict__ wv, const float* __restrict__ bv,
                            const float* __restrict__ scaler, int B) {
    int id = blockIdx.x * blockDim.x + threadIdx.x;
    if (id >= B * 512) return;
    int b = id >> 9, r = id & 511;
    const float* w = (r < 256) ? (w1 + (size_t)r * DIMC) : (wv + (size_t)(r - 256) * DIMC);
    float base = (r < 256) ? b1[r] : bv[r - 256];
    const float* mn = g_mean + b * DIMC;
    float s = 0.f;
#pragma unroll 8
    for (int c = 0; c < DIMC; c++) s += w[c] * scaler[c] * mn[c];
    g_bb[id] = base + s;
}

// ---------------- kernel 3: weight fp16 split ([fc1;fcv]) ----------------
__global__ void convw_kernel(const float* __restrict__ w1, const float* __restrict__ wv) {
    int i = blockIdx.x * blockDim.x + threadIdx.x;
    if (i < 65536) hsplit(w1[i], g_w1hi[i], g_w1lo[i]);
    else if (i < 131072) hsplit(wv[i - 65536], g_w1hi[i], g_w1lo[i]);
}

// ---------------- kernel 4: transpose+split [b][c][S] -> [b][s][c] hi/lo ----------------
__global__ void convx_kernel(const float* __restrict__ src, __half* __restrict__ dhi,
                             __half* __restrict__ dlo, int S) {
    __shared__ float t[32][33];
    int s0 = blockIdx.x * 32, c0 = blockIdx.y * 32, b = blockIdx.z;
    int tx = threadIdx.x, ty = threadIdx.y;
#pragma unroll
    for (int i = 0; i < 4; i++)
        t[ty + i * 8][tx] = src[((size_t)(b * DIMC + c0 + ty + i * 8)) * S + s0 + tx];
    __syncthreads();
#pragma unroll
    for (int i = 0; i < 4; i++) {
        int s = s0 + ty + i * 8;
        float v = t[tx][ty + i * 8];
        __half h, l;
        hsplit(v, h, l);
        size_t o = ((size_t)b * S + s) * DIMC + c0 + tx;
        dhi[o] = h;
        dlo[o] = l;
    }
}

// ---------------- kernel 5: generic HMMA fp16-split GEMM (pooled conv) ----------------
__global__ __launch_bounds__(256)
void gemm_hmma_kernel(const __half* __restrict__ whi, const __half* __restrict__ wlo,
                      const __half* __restrict__ xhi, const __half* __restrict__ xlo,
                      const float* __restrict__ bias, float* __restrict__ O,
                      int M, int S, int biasPerBatch) {
    extern __shared__ __align__(1024) char sm[];
    const int tid = threadIdx.x, lane = tid & 31, warp = tid >> 5;
    const int b = blockIdx.z, n0 = blockIdx.x * 128, m0 = blockIdx.y * 128;
    const int wm = (warp >> 2) * 64, wn = (warp & 3) * 32;

    const __half* srcs[4] = {
        whi + (size_t)m0 * DIMC, wlo + (size_t)m0 * DIMC,
        xhi + ((size_t)b * S + n0) * DIMC, xlo + ((size_t)b * S + n0) * DIMC };
    const uint32_t smb = smem_u32(sm);

    float acc[4][4][4];
#pragma unroll
    for (int i = 0; i < 4; i++)
#pragma unroll
        for (int j = 0; j < 4; j++)
#pragma unroll
            for (int k = 0; k < 4; k++) acc[i][j][k] = 0.f;

    auto load_stage = [&](int stage, int kc) {
#pragma unroll
        for (int t = 0; t < 4; t++) {
#pragma unroll
            for (int i = 0; i < 2; i++) {
                int chunkid = tid + 256 * i;
                int row = chunkid >> 2, c = chunkid & 3;
                cp_async16(smb + stage * 32768 + t * 8192 + sw_off(row, c),
                           srcs[t] + (size_t)row * DIMC + kc * 32 + c * 8);
            }
        }
        CP_COMMIT();
    };
    const int rl = lane & 7, sel = lane >> 3;

    load_stage(0, 0);
    int stage = 0;
    for (int kc = 0; kc < 8; kc++) {
        if (kc + 1 < 8) { load_stage(stage ^ 1, kc + 1); CP_WAIT(1); }
        else            { CP_WAIT(0); }
        __syncthreads();
        const uint32_t base = smb + stage * 32768;
#pragma unroll
        for (int ks = 0; ks < 2; ks++) {
            uint32_t ahi[4][4], alo[4][4];
#pragma unroll
            for (int mt = 0; mt < 4; mt++) {
                int row = wm + mt * 16 + (sel & 1) * 8 + rl;
                int ch = ks * 2 + (sel >> 1);
                uint32_t o = sw_off(row, ch);
                ldsm4(ahi[mt], base + o);
                ldsm4(alo[mt], base + 8192 + o);
            }
            uint32_t bhi[4][2], blo[4][2];
#pragma unroll
            for (int p = 0; p < 2; p++) {
                int row = wn + p * 16 + (sel >> 1) * 8 + rl;
                int ch = ks * 2 + (sel & 1);
                uint32_t o = sw_off(row, ch);
                uint32_t r4[4];
                ldsm4(r4, base + 16384 + o);
                bhi[2 * p][0] = r4[0]; bhi[2 * p][1] = r4[1];
                bhi[2 * p + 1][0] = r4[2]; bhi[2 * p + 1][1] = r4[3];
                ldsm4(r4, base + 24576 + o);
                blo[2 * p][0] = r4[0]; blo[2 * p][1] = r4[1];
                blo[2 * p + 1][0] = r4[2]; blo[2 * p + 1][1] = r4[3];
            }
#pragma unroll
            for (int mt = 0; mt < 4; mt++)
#pragma unroll
                for (int nt = 0; nt < 4; nt++) {
                    mma_f16(acc[mt][nt], ahi[mt], bhi[nt]);
                    mma_f16(acc[mt][nt], ahi[mt], blo[nt]);
                    mma_f16(acc[mt][nt], alo[mt], bhi[nt]);
                }
        }
        __syncthreads();
        stage ^= 1;
    }
    const int g = lane >> 2, tig = lane & 3;
    const int bofs = biasPerBatch ? b * M : 0;
#pragma unroll
    for (int mt = 0; mt < 4; mt++) {
        int r0 = m0 + wm + mt * 16 + g;
        float b0v = bias[bofs + r0];
        float b1v = bias[bofs + r0 + 8];
        float* orow0 = O + ((size_t)b * M + r0) * S + n0;
        float* orow1 = orow0 + (size_t)8 * S;
#pragma unroll
        for (int nt = 0; nt < 4; nt++) {
            int col = wn + nt * 8 + 2 * tig;
            *reinterpret_cast<float2*>(orow0 + col) =
                make_float2(acc[mt][nt][0] + b0v, acc[mt][nt][1] + b0v);
            *reinterpret_cast<float2*>(orow1 + col) =
                make_float2(acc[mt][nt][2] + b1v, acc[mt][nt][3] + b1v);
        }
    }
}

// ---------------- kernel 6: centers (pooled pipeline -> cns, vcs) ----------------
__global__ __launch_bounds__(256)
void centers_kernel(const float* __restrict__ w1, const float* __restrict__ bb1,
                    const float* __restrict__ w2, const float* __restrict__ bb2) {
    const int tid = threadIdx.x;
    const int bbk = blockIdx.x;           // b*32 + h*4 + win
    const int b = bbk >> 5;
    const int h = (bbk >> 2) & 7;
    const int fi = (bbk >> 1) & 1;
    const int fj = bbk & 1;

    __shared__ float a8[2048];
    __shared__ float hbuf[HIDM * 64];
    __shared__ float w1s[HIDM * HDIM], b1s[HIDM], w2s[HDIM * HIDM], b2s[HDIM];
    __shared__ float ctrs[128], vcs[128], cavg[128];
    __shared__ float cnorm[4];

    for (int i = tid; i < HIDM * HDIM; i += 256) { w1s[i] = w1[i]; w2s[i] = w2[i]; }
    if (tid < HIDM) b1s[tid] = bb1[tid];
    if (tid < HDIM) b2s[tid] = bb2[tid];

    for (int pass = 0; pass < 2; pass++) {
        const int base_row = (pass == 0) ? (256 + h * HDIM) : (h * HDIM);
        float* dst = (pass == 0) ? vcs : ctrs;
        __syncthreads();
#pragma unroll
        for (int rep = 0; rep < 8; rep++) {
            int e = rep * 256 + tid;
            int c = e >> 6, pos = e & 63;
            a8[c * 64 + pos] = g_pxv[((size_t)(b * 512) + base_row + c) * 256
                                     + (fi * 8 + (pos >> 3)) * 16 + fj * 8 + (pos & 7)];
        }
        __syncthreads();
        if (tid < 128) {
            int m = tid >> 5, c = tid & 31, qi = m >> 1, qj = m & 1;
            float s = 0.f;
#pragma unroll
            for (int u = 0; u < 4; u++)
#pragma unroll
                for (int v2 = 0; v2 < 4; v2++)
                    s += a8[c * 64 + (qi * 4 + u) * 8 + qj * 4 + v2];
            cavg[tid] = s * (1.f / 16.f);
        }
        for (int eh = tid; eh < HIDM * 64; eh += 256) {
            int j = eh >> 6, p = eh & 63;
            float s = b1s[j];
#pragma unroll
            for (int c = 0; c < HDIM; c++) s += w1s[j * HDIM + c] * a8[c * 64 + p];
            hbuf[eh] = 0.5f * s * (1.f + erff(s * 0.70710678118654752440f));
        }
        __syncthreads();
        for (int eo = tid; eo < 2048; eo += 256) {
            int c = eo >> 6, p = eo & 63;
            float s = b2s[c];
#pragma unroll
            for (int j = 0; j < HIDM; j++) s += w2s[c * HIDM + j] * hbuf[j * 64 + p];
            a8[eo] = s;
        }
        __syncthreads();
        if (tid < 128) {
            int m = tid >> 5, c = tid & 31, qi = m >> 1, qj = m & 1;
            float mx = -INFINITY;
#pragma unroll
            for (int u = 0; u < 4; u++)
#pragma unroll
                for (int v2 = 0; v2 < 4; v2++)
                    mx = fmaxf(mx, a8[c * 64 + (qi * 4 + u) * 8 + qj * 4 + v2]);
            dst[tid] = cavg[tid] + mx;
        }
        __syncthreads();
    }

    if (tid < 4) {
        float s = 0.f;
#pragma unroll
        for (int c = 0; c < HDIM; c++) { float v = ctrs[tid * 32 + c]; s += v * v; }
        cnorm[tid] = fmaxf(sqrtf(s), 1e-12f);
    }
    __syncthreads();
    if (tid < 128) {
        g_cns[(size_t)bbk * 128 + tid] = ctrs[tid] / cnorm[tid >> 5];
        g_vcs[(size_t)bbk * 128 + tid] = vcs[tid];
    }
}

// ---------------- kernel 7: main fused GEMM (fc1 only) + sim/argmax epilogue ----------------
__global__ __launch_bounds__(256)
void gemm_sim_kernel(const __half* __restrict__ whi, const __half* __restrict__ wlo,
                     const __half* __restrict__ xhi, const __half* __restrict__ xlo,
                     const float* __restrict__ alphaP, const float* __restrict__ betaP) {
    extern __shared__ __align__(1024) char sm[];   // mainloop 64KB; epilogue 128x132 fp32
    __shared__ float cns_s[4][2][4][32];
    const int tid = threadIdx.x, lane = tid & 31, warp = tid >> 5;
    const int b = blockIdx.z, n0 = blockIdx.x * 128, m0 = blockIdx.y * 128;
    const int wm = (warp >> 2) * 64, wn = (warp & 3) * 32;

    const __half* srcs[4] = {
        whi + (size_t)m0 * DIMC, wlo + (size_t)m0 * DIMC,
        xhi + ((size_t)b * SPAT + n0) * DIMC, xlo + ((size_t)b * SPAT + n0) * DIMC };
    const uint32_t smb = smem_u32(sm);

    float acc[4][4][4];
#pragma unroll
    for (int i = 0; i < 4; i++)
#pragma unroll
        for (int j = 0; j < 4; j++)
#pragma unroll
            for (int k = 0; k < 4; k++) acc[i][j][k] = 0.f;

    auto load_stage = [&](int stage, int kc) {
#pragma unroll
        for (int t = 0; t < 4; t++) {
#pragma unroll
            for (int i = 0; i < 2; i++) {
                int chunkid = tid + 256 * i;
                int row = chunkid >> 2, c = chunkid & 3;
                cp_async16(smb + stage * 32768 + t * 8192 + sw_off(row, c),
                           srcs[t] + (size_t)row * DIMC + kc * 32 + c * 8);
            }
        }
        CP_COMMIT();
    };
    const int rl = lane & 7, sel = lane >> 3;

    load_stage(0, 0);
    int stage = 0;
    for (int kc = 0; kc < 8; kc++) {
        if (kc + 1 < 8) { load_stage(stage ^ 1, kc + 1); CP_WAIT(1); }
        else            { CP_WAIT(0); }
        __syncthreads();
        const uint32_t base = smb + stage * 32768;
#pragma unroll
        for (int ks = 0; ks < 2; ks++) {
            uint32_t ahi[4][4], alo[4][4];
#pragma unroll
            for (int mt = 0; mt < 4; mt++) {
                int row = wm + mt * 16 + (sel & 1) * 8 + rl;
                int ch = ks * 2 + (sel >> 1);
                uint32_t o = sw_off(row, ch);
                ldsm4(ahi[mt], base + o);
                ldsm4(alo[mt], base + 8192 + o);
            }
            uint32_t bhi[4][2], blo[4][2];
#pragma unroll
            for (int p = 0; p < 2; p++) {
                int row = wn + p * 16 + (sel >> 1) * 8 + rl;
                int ch = ks * 2 + (sel & 1);
                uint32_t o = sw_off(row, ch);
                uint32_t r4[4];
                ldsm4(r4, base + 16384 + o);
                bhi[2 * p][0] = r4[0]; bhi[2 * p][1] = r4[1];
                bhi[2 * p + 1][0] = r4[2]; bhi[2 * p + 1][1] = r4[3];
                ldsm4(r4, base + 24576 + o);
                blo[2 * p][0] = r4[0]; blo[2 * p][1] = r4[1];
                blo[2 * p + 1][0] = r4[2]; blo[2 * p + 1][1] = r4[3];
            }
#pragma unroll
            for (int mt = 0; mt < 4; mt++)
#pragma unroll
                for (int nt = 0; nt < 4; nt++) {
                    mma_f16(acc[mt][nt], ahi[mt], bhi[nt]);
                    mma_f16(acc[mt][nt], ahi[mt], blo[nt]);
                    mma_f16(acc[mt][nt], alo[mt], bhi[nt]);
                }
        }
        __syncthreads();
        stage ^= 1;
    }

    // ---- epilogue: x1 tile -> smem, then per-token norms + sims + argmax ----
    const int h0 = m0 >> 5;                 // first head of this CTA (0 or 4)
    const int fi = (n0 >= 2048) ? 1 : 0;
    float* epi = (float*)sm;                // [128 rows][132 stride]
    {
        const int g = lane >> 2, tig = lane & 3;
#pragma unroll
        for (int mt = 0; mt < 4; mt++) {
            int lr0 = wm + mt * 16 + g;
            float b0v = g_bb[b * 512 + m0 + lr0];
            float b1v = g_bb[b * 512 + m0 + lr0 + 8];
#pragma unroll
            for (int nt = 0; nt < 4; nt++) {
                int col = wn + nt * 8 + 2 * tig;
                epi[lr0 * 132 + col]           = acc[mt][nt][0] + b0v;
                epi[lr0 * 132 + col + 1]       = acc[mt][nt][1] + b0v;
                epi[(lr0 + 8) * 132 + col]     = acc[mt][nt][2] + b1v;
                epi[(lr0 + 8) * 132 + col + 1] = acc[mt][nt][3] + b1v;
            }
        }
    }
    // load centers for this CTA's 4 heads x 2 windows
    for (int i = tid; i < 1024; i += 256) {
        int hl = i >> 8, fjj = (i >> 7) & 1, m = (i >> 5) & 3, d = i & 31;
        int bbk = b * 32 + (h0 + hl) * 4 + fi * 2 + fjj;
        cns_s[hl][fjj][m][d] = g_cns[(size_t)bbk * 128 + m * 32 + d];
    }
    __syncthreads();

    const float alpha = alphaP[0], beta = betaP[0];
    const int hl = tid >> 6, tp = tid & 63;
#pragma unroll
    for (int rep = 0; rep < 2; rep++) {
        int tk = tp * 2 + rep;
        int s = n0 + tk;
        int hj = s & 63, fj = hj >> 5;
        int nw = ((s >> 6) & 31) * 32 + (hj & 31);
        float nrm = 0.f, dm[4] = {0.f, 0.f, 0.f, 0.f};
#pragma unroll
        for (int d = 0; d < 32; d++) {
            float v = epi[(hl * 32 + d) * 132 + tk];
            nrm += v * v;
#pragma unroll
            for (int m = 0; m < 4; m++) dm[m] += cns_s[hl][fj][m][d] * v;
        }
        float inv = 1.f / fmaxf(sqrtf(nrm), 1e-12f);
        float best = -1.f; int bm = 0;
#pragma unroll
        for (int m = 0; m < 4; m++) {
            float sg = 1.f / (1.f + expf(-(beta + alpha * dm[m] * inv)));
            if (sg > best) { best = sg; bm = m; }
        }
        size_t idx = ((size_t)(b * 8 + h0 + hl) * 4 + fi * 2 + fj) * 1024 + nw;
        g_sim[idx] = best;
        g_mstar[idx] = (unsigned char)bm;
    }
}

// ---------------- kernel 8: t = sum sim*x  (grid: 4 cgroups x 4 win x B) ----------------
__global__ __launch_bounds__(256)
void taccum_kernel() {
    const int cg = blockIdx.x;            // 0..3 -> channels cg*64..cg*64+64
    const int win = blockIdx.y;           // 0..3
    const int b = blockIdx.z;
    const int fi = win >> 1, fj = win & 1;
    const int tid = threadIdx.x;
    const int cp = tid & 31;              // channel pair: c = cg*64 + 2*cp
    const int h = tid >> 5;               // head 0..7

    __shared__ float stage[64][64];       // [t][c] fp32 reconstructed, 16KB
    __shared__ float ws[8][4][64];        // masked sims, 8KB

    float2 acc[4];
#pragma unroll
    for (int m = 0; m < 4; m++) acc[m] = make_float2(0.f, 0.f);

    for (int chunk = 0; chunk < 16; chunk++) {
#pragma unroll
        for (int it = 0; it < 16; it++) {
            int i = it * 256 + tid;
            int t = i >> 6, c = i & 63;
            int n = chunk * 64 + t;
            int s = (fi * 32 + (n >> 5)) * 64 + fj * 32 + (n & 31);
            size_t off = ((size_t)b * SPAT + s) * DIMC + cg * 64 + c;
            stage[t][c] = __half2float(g_xthi[off]) + __half2float(g_xtlo[off]);
        }
#pragma unroll
        for (int it = 0; it < 8; it++) {
            int i = it * 256 + tid;           // 8*4*64 = 2048 entries
            int hh = i >> 8, mm = (i >> 6) & 3, t = i & 63;
            size_t sb = ((size_t)(b * 8 + hh) * 4 + win) * 1024 + chunk * 64 + t;
            ws[hh][mm][t] = (g_mstar[sb] == (unsigned char)mm) ? g_sim[sb] : 0.f;
        }
        __syncthreads();
#pragma unroll 4
        for (int t = 0; t < 64; t++) {
            float2 xv = *reinterpret_cast<const float2*>(&stage[t][2 * cp]);
#pragma unroll
            for (int m = 0; m < 4; m++) {
                float w = ws[h][m][t];
                acc[m].x += w * xv.x;
                acc[m].y += w * xv.y;
            }
        }
        __syncthreads();
    }
#pragma unroll
    for (int m = 0; m < 4; m++) {
        size_t o = (((size_t)(b * 4 + win) * 8 + h) * 4 + m) * 256 + cg * 64 + 2 * cp;
        *reinterpret_cast<float2*>(&g_t[o]) = acc[m];
    }
}

// ---------------- kernel 9: outm + y fused (grid B*32 = (b,h,win)) ----------------
// outm[m][d] = (Wv[h*32+d,:].t[m] + sig[m]*bbv[d] + vcs)/(cnt[m]+1);  y[m][o] = W2[o,h-blk].outm[m]
__global__ __launch_bounds__(256)
void outm_y_kernel(const float* __restrict__ wv, const float* __restrict__ w2) {
    const int bbk = blockIdx.x;           // b*32 + h*4 + win
    const int b = bbk >> 5;
    const int h = (bbk >> 2) & 7;
    const int win = bbk & 3;
    const int tid = threadIdx.x, lane = tid & 31, warp = tid >> 5;

    __shared__ float t_s[4][256];         // 4KB
    __shared__ float wbuf[8448];          // 33KB flat; Wv view [d*257+c], W2 view [o*33+d]
    __shared__ float sigs[4], cnts[4];
    __shared__ float outm_s[128];

    // load t
    for (int i = tid; i < 1024; i += 256)
        t_s[i >> 8][i & 255] = g_t[(((size_t)(b * 4 + win) * 8 + h) * 4 + (i >> 8)) * 256 + (i & 255)];
    // sig/cnt: warps 0..3 handle m=warp
    if (warp < 4) {
        float s = 0.f, c = 0.f;
        for (int n = lane; n < 1024; n += 32) {
            size_t sb = ((size_t)(b * 8 + h) * 4 + win) * 1024 + n;
            if (g_mstar[sb] == (unsigned char)warp) { s += g_sim[sb]; c += 1.f; }
        }
        for (int o = 16; o; o >>= 1) {
            s += __shfl_down_sync(0xffffffffu, s, o);
            c += __shfl_down_sync(0xffffffffu, c, o);
        }
        if (lane == 0) { sigs[warp] = s; cnts[warp] = c; }
    }
    // load Wv rows h*32..h*32+32 of w_fcv (FIX: no +256 here — that offset is only for g_bb)
    for (int i = tid; i < 32 * 256; i += 256) {
        int r = i >> 8, c = i & 255;
        wbuf[r * 257 + c] = wv[(size_t)(h * HDIM + r) * DIMC + c];
    }
    __syncthreads();

    if (tid < 128) {
        int m = tid >> 5, d = tid & 31;
        float s = 0.f;
#pragma unroll 8
        for (int c = 0; c < DIMC; c++) s += wbuf[d * 257 + c] * t_s[m][c];
        float bbv = g_bb[b * 512 + 256 + h * HDIM + d];
        float vc = g_vcs[(size_t)bbk * 128 + m * 32 + d];
        outm_s[tid] = (s + sigs[m] * bbv + vc) / (cnts[m] + 1.f);
    }
    __syncthreads();
    // W2 block [256 o][32 d], stride-33 (256*33 = 8448 fits exactly)
    for (int i = tid; i < 256 * 32; i += 256) {
        int o = i >> 5, d = i & 31;
        wbuf[o * 33 + d] = w2[(size_t)o * DIMC + h * HDIM + d];
    }
    __syncthreads();
    {
        int o = tid;
        float yv[4] = {0.f, 0.f, 0.f, 0.f};
#pragma unroll
        for (int d = 0; d < HDIM; d++) {
            float w = wbuf[o * 33 + d];
#pragma unroll
            for (int m = 0; m < 4; m++) yv[m] += w * outm_s[m * 32 + d];
        }
#pragma unroll
        for (int m = 0; m < 4; m++)
            g_y[(size_t)bbk * 1024 + m * 256 + o] = yv[m];
    }
}

// ---------------- kernel 10: combine -> final output ----------------
__global__ __launch_bounds__(256)
void combine_kernel(const float* __restrict__ b2, float* __restrict__ out) {
    const int o0 = blockIdx.x * 32;
    const int win = blockIdx.y;
    const int batch = blockIdx.z;
    const int fi = win >> 1, fj = win & 1;
    const int tid = threadIdx.x, lane = tid & 31, warp = tid >> 5;

    __shared__ float ys[8][4][33];
    __shared__ float b2s[32];

    for (int i = tid; i < 8 * 4 * 32; i += 256) {
        int h = i >> 7, m = (i >> 5) & 3, o = i & 31;
        ys[h][m][o] = g_y[((size_t)(batch * 8 + h) * 4 + win) * 1024 + m * 256 + o0 + o];
    }
    if (tid < 32) b2s[tid] = b2[o0 + tid];
    __syncthreads();

#pragma unroll
    for (int r = 0; r < 4; r++) {
        int wi = warp * 4 + r;
        int n = wi * 32 + lane;
        float simr[8];
        int mr[8];
#pragma unroll
        for (int h = 0; h < 8; h++) {
            size_t sb = ((size_t)(batch * 8 + h) * 4 + win) * 1024 + n;
            simr[h] = g_sim[sb];
            mr[h] = g_mstar[sb];
        }
        int s = (fi * 32 + wi) * 64 + fj * 32 + lane;
        float* op = out + ((size_t)batch * DIMC + o0) * SPAT + s;
#pragma unroll
        for (int o = 0; o < 32; o++) {
            float acc = b2s[o];
#pragma unroll
            for (int h = 0; h < 8; h++) acc += simr[h] * ys[h][mr[h]][o];
            op[(size_t)o * SPAT] = acc;
        }
    }
}

// ---------------- launcher ----------------
extern "C" void kernel_launch(void* const* d_in, const int* in_sizes, int n_in,
                              void* d_out, int out_size) {
    const float* x      = (const float*)d_in[0];
    const float* scaler = (const float*)d_in[1];
    const float* w_fc1  = (const float*)d_in[2];
    const float* b_fc1  = (const float*)d_in[3];
    const float* w_fcv  = (const float*)d_in[4];
    const float* b_fcv  = (const float*)d_in[5];
    const float* w_fc2  = (const float*)d_in[6];
    const float* b_fc2  = (const float*)d_in[7];
    const float* alpha  = (const float*)d_in[8];
    const float* beta   = (const float*)d_in[9];
    const float* off_w1 = (const float*)d_in[10];
    const float* off_b1 = (const float*)d_in[11];
    const float* off_w2 = (const float*)d_in[12];
    const float* off_b2 = (const float*)d_in[13];
    float* out = (float*)d_out;

    int B = in_sizes[0] / (DIMC * SPAT);
    if (B > MAXB) B = MAXB;

    float *p_pool, *p_bb, *p_pxv;
    __half *p_w1h, *p_w1l, *p_xth, *p_xtl, *p_pth, *p_ptl;
    cudaGetSymbolAddress((void**)&p_pool, g_pool);
    cudaGetSymbolAddress((void**)&p_bb,   g_bb);
    cudaGetSymbolAddress((void**)&p_pxv,  g_pxv);
    cudaGetSymbolAddress((void**)&p_w1h,  g_w1hi);
    cudaGetSymbolAddress((void**)&p_w1l,  g_w1lo);
    cudaGetSymbolAddress((void**)&p_xth,  g_xthi);
    cudaGetSymbolAddress((void**)&p_xtl,  g_xtlo);
    cudaGetSymbolAddress((void**)&p_pth,  g_pthi);
    cudaGetSymbolAddress((void**)&p_ptl,  g_ptlo);

    cudaFuncSetAttribute(gemm_hmma_kernel, cudaFuncAttributeMaxDynamicSharedMemorySize, 65536);
    cudaFuncSetAttribute(gemm_sim_kernel,  cudaFuncAttributeMaxDynamicSharedMemorySize, 67584);

    // 1. pooled x (16x16) + spatial mean, then adjusted biases
    pool_kernel<<<B * DIMC, 256>>>(x);
    bias_kernel<<<(B * 512 + 255) / 256, 256>>>(w_fc1, b_fc1, w_fcv, b_fcv, scaler, B);
    // 2. fp16 weight split, x transpose+split, pooled transpose+split
    convw_kernel<<<512, 256>>>(w_fc1, w_fcv);
    {
        dim3 g(SPAT / 32, DIMC / 32, B);
        convx_kernel<<<g, dim3(32, 8)>>>(x, p_xth, p_xtl, SPAT);
    }
    {
        dim3 g(256 / 32, DIMC / 32, B);
        convx_kernel<<<g, dim3(32, 8)>>>(p_pool, p_pth, p_ptl, 256);
    }
    // 3. pooled conv (fc1+fcv on pooled x)
    {
        dim3 grid(256 / 128, 512 / 128, B);
        gemm_hmma_kernel<<<grid, 256, 65536>>>(p_w1h, p_w1l, p_pth, p_ptl, p_bb, p_pxv, 512, 256, 1);
    }
    // 4. centers + normalized cn + value centers (tiny, pooled-only)
    centers_kernel<<<B * 32, 256>>>(off_w1, off_b1, off_w2, off_b2);
    // 5. main fused GEMM: fc1(x) + per-token norm/sim/argmax (no x1 materialization)
    {
        dim3 grid(SPAT / 128, 256 / 128, B);
        gemm_sim_kernel<<<grid, 256, 67584>>>(p_w1h, p_w1l, p_xth, p_xtl, alpha, beta);
    }
    // 6. t = sum sim*x per cluster (well-parallelized: 16*B blocks)
    {
        dim3 grid(4, 4, B);
        taccum_kernel<<<grid, 256>>>();
    }
    // 7. outm + y fused
    outm_y_kernel<<<B * 32, 256>>>(w_fcv, w_fc2);
    // 8. combine -> final output
    {
        dim3 grid(8, 4, B);
        combine_kernel<<<grid, 256>>>(b_fc2, out);
    }
}

// round 11
// speedup vs baseline: 1.8239x; 1.0459x over previous
#include <cuda_runtime.h>
#include <cuda_fp16.h>
#include <cstdint>
#include <math.h>

// ---------------- problem constants ----------------
#define DIMC   256
#define SPAT   4096
#define NHEAD  8
#define HDIM   32
#define HIDM   53
#define MAXB   16

// ---------------- device scratch ----------------
__device__ float g_mean[MAXB * DIMC];
__device__ float g_bb[MAXB * 512];                         // adjusted bias [fc1;fcv]
__device__ float g_pool[MAXB * DIMC * 256];                // 16x16 pooled x (avg 4x4)
__device__ __half g_w1hi[512 * DIMC], g_w1lo[512 * DIMC];  // [fc1;fcv] fp16 split
__device__ __half g_xthi[(size_t)MAXB * SPAT * DIMC];      // X^T [b][s][k] fp16 split
__device__ __half g_xtlo[(size_t)MAXB * SPAT * DIMC];
__device__ __half g_pthi[MAXB * 256 * DIMC];               // pooled^T [b][p][k]
__device__ __half g_ptlo[MAXB * 256 * DIMC];
__device__ float g_pxv[MAXB * 512 * 256];                  // pooled fc1+fcv out
__device__ float g_cns[512 * 128];                         // normalized centers
__device__ float g_vcs[512 * 128];                         // value centers
__device__ float g_sim[(size_t)MAXB * 32 * 1024];          // per-(b,h,win) token sim
__device__ unsigned char g_mstar[(size_t)MAXB * 32 * 1024];
__device__ float g_t[(size_t)MAXB * 4 * 8 * 4 * 256];      // [b][win][h][m][c]
__device__ float g_y[512 * 1024];                          // W2 . outm

// ---------------- PTX helpers ----------------
__device__ __forceinline__ uint32_t smem_u32(const void* p) {
    uint32_t a;
    asm("{ .reg .u64 t; cvta.to.shared.u64 t, %1; cvt.u32.u64 %0, t; }" : "=r"(a) : "l"(p));
    return a;
}
__device__ __forceinline__ void cp_async16(uint32_t s, const void* g) {
    asm volatile("cp.async.cg.shared.global [%0], [%1], 16;" :: "r"(s), "l"(g));
}
#define CP_COMMIT() asm volatile("cp.async.commit_group;" ::: "memory")
#define CP_WAIT(n)  asm volatile("cp.async.wait_group %0;" :: "n"(n) : "memory")

__device__ __forceinline__ void ldsm4(uint32_t* r, uint32_t a) {
    asm volatile("ldmatrix.sync.aligned.m8n8.x4.shared.b16 {%0,%1,%2,%3}, [%4];"
        : "=r"(r[0]), "=r"(r[1]), "=r"(r[2]), "=r"(r[3]) : "r"(a));
}
__device__ __forceinline__ void mma_f16(float* d, const uint32_t* a, const uint32_t* b) {
    asm volatile("mma.sync.aligned.m16n8k16.row.col.f32.f16.f16.f32 "
        "{%0,%1,%2,%3}, {%4,%5,%6,%7}, {%8,%9}, {%0,%1,%2,%3};"
        : "+f"(d[0]), "+f"(d[1]), "+f"(d[2]), "+f"(d[3])
        : "r"(a[0]), "r"(a[1]), "r"(a[2]), "r"(a[3]), "r"(b[0]), "r"(b[1]));
}
__device__ __forceinline__ void hsplit(float v, __half& h, __half& l) {
    h = __float2half_rn(v);
    l = __float2half_rn(v - __half2float(h));
}
// smem tile: 128 rows x 32 f16 (64B/row), 16B-chunk XOR swizzle
__device__ __forceinline__ uint32_t sw_off(int row, int chunk) {
    return (uint32_t)(row * 64 + ((chunk ^ ((row >> 1) & 3)) << 4));
}

// ---------------- kernel 1: 4x4 avg-pool (16x16) + spatial mean ----------------
__global__ __launch_bounds__(256)
void pool_kernel(const float* __restrict__ x) {
    int bc = blockIdx.x;                        // B*256
    const float* p = x + (size_t)bc * SPAT;
    __shared__ float sm[4096];
    __shared__ float red[256];
    int tid = threadIdx.x;
    for (int i = tid; i < 4096; i += 256) sm[i] = p[i];
    __syncthreads();
    int pi = tid >> 4, pj = tid & 15;
    float s = 0.f;
#pragma unroll
    for (int u = 0; u < 4; u++)
#pragma unroll
        for (int v = 0; v < 4; v++)
            s += sm[(pi * 4 + u) * 64 + pj * 4 + v];
    g_pool[(size_t)bc * 256 + tid] = s * (1.f / 16.f);
    red[tid] = s;
    __syncthreads();
    for (int off = 128; off > 0; off >>= 1) {
        if (tid < off) red[tid] += red[tid + off];
        __syncthreads();
    }
    if (tid == 0) g_mean[bc] = red[0] * (1.f / (float)SPAT);
}

// ---------------- kernel 2: adjusted bias ----------------
__global__ void bias_kernel(const float* __restrict__ w1, const float* __restrict__ b1,
                            const float* __restrict__ wv, const float* __restrict__ bv,
                            const float* __restrict__ scaler, int B) {
    int id = blockIdx.x * blockDim.x + threadIdx.x;
    if (id >= B * 512) return;
    int b = id >> 9, r = id & 511;
    const float* w = (r < 256) ? (w1 + (size_t)r * DIMC) : (wv + (size_t)(r - 256) * DIMC);
    float base = (r < 256) ? b1[r] : bv[r - 256];
    const float* mn = g_mean + b * DIMC;
    float s = 0.f;
#pragma unroll 8
    for (int c = 0; c < DIMC; c++) s += w[c] * scaler[c] * mn[c];
    g_bb[id] = base + s;
}

// ---------------- kernel 3: weight fp16 split ([fc1;fcv]) ----------------
__global__ void convw_kernel(const float* __restrict__ w1, const float* __restrict__ wv) {
    int i = blockIdx.x * blockDim.x + threadIdx.x;
    if (i < 65536) hsplit(w1[i], g_w1hi[i], g_w1lo[i]);
    else if (i < 131072) hsplit(wv[i - 65536], g_w1hi[i], g_w1lo[i]);
}

// ---------------- kernel 4: transpose+split [b][c][S] -> [b][s][c] hi/lo ----------------
__global__ void convx_kernel(const float* __restrict__ src, __half* __restrict__ dhi,
                             __half* __restrict__ dlo, int S) {
    __shared__ float t[32][33];
    int s0 = blockIdx.x * 32, c0 = blockIdx.y * 32, b = blockIdx.z;
    int tx = threadIdx.x, ty = threadIdx.y;
#pragma unroll
    for (int i = 0; i < 4; i++)
        t[ty + i * 8][tx] = src[((size_t)(b * DIMC + c0 + ty + i * 8)) * S + s0 + tx];
    __syncthreads();
#pragma unroll
    for (int i = 0; i < 4; i++) {
        int s = s0 + ty + i * 8;
        float v = t[tx][ty + i * 8];
        __half h, l;
        hsplit(v, h, l);
        size_t o = ((size_t)b * S + s) * DIMC + c0 + tx;
        dhi[o] = h;
        dlo[o] = l;
    }
}

// ---------------- kernel 5: generic HMMA fp16-split GEMM (pooled conv) ----------------
__global__ __launch_bounds__(256)
void gemm_hmma_kernel(const __half* __restrict__ whi, const __half* __restrict__ wlo,
                      const __half* __restrict__ xhi, const __half* __restrict__ xlo,
                      const float* __restrict__ bias, float* __restrict__ O,
                      int M, int S, int biasPerBatch) {
    extern __shared__ __align__(1024) char sm[];
    const int tid = threadIdx.x, lane = tid & 31, warp = tid >> 5;
    const int b = blockIdx.z, n0 = blockIdx.x * 128, m0 = blockIdx.y * 128;
    const int wm = (warp >> 2) * 64, wn = (warp & 3) * 32;

    const __half* srcs[4] = {
        whi + (size_t)m0 * DIMC, wlo + (size_t)m0 * DIMC,
        xhi + ((size_t)b * S + n0) * DIMC, xlo + ((size_t)b * S + n0) * DIMC };
    const uint32_t smb = smem_u32(sm);

    float acc[4][4][4];
#pragma unroll
    for (int i = 0; i < 4; i++)
#pragma unroll
        for (int j = 0; j < 4; j++)
#pragma unroll
            for (int k = 0; k < 4; k++) acc[i][j][k] = 0.f;

    auto load_stage = [&](int stage, int kc) {
#pragma unroll
        for (int t = 0; t < 4; t++) {
#pragma unroll
            for (int i = 0; i < 2; i++) {
                int chunkid = tid + 256 * i;
                int row = chunkid >> 2, c = chunkid & 3;
                cp_async16(smb + stage * 32768 + t * 8192 + sw_off(row, c),
                           srcs[t] + (size_t)row * DIMC + kc * 32 + c * 8);
            }
        }
        CP_COMMIT();
    };
    const int rl = lane & 7, sel = lane >> 3;

    load_stage(0, 0);
    int stage = 0;
    for (int kc = 0; kc < 8; kc++) {
        if (kc + 1 < 8) { load_stage(stage ^ 1, kc + 1); CP_WAIT(1); }
        else            { CP_WAIT(0); }
        __syncthreads();
        const uint32_t base = smb + stage * 32768;
#pragma unroll
        for (int ks = 0; ks < 2; ks++) {
            uint32_t ahi[4][4], alo[4][4];
#pragma unroll
            for (int mt = 0; mt < 4; mt++) {
                int row = wm + mt * 16 + (sel & 1) * 8 + rl;
                int ch = ks * 2 + (sel >> 1);
                uint32_t o = sw_off(row, ch);
                ldsm4(ahi[mt], base + o);
                ldsm4(alo[mt], base + 8192 + o);
            }
            uint32_t bhi[4][2], blo[4][2];
#pragma unroll
            for (int p = 0; p < 2; p++) {
                int row = wn + p * 16 + (sel >> 1) * 8 + rl;
                int ch = ks * 2 + (sel & 1);
                uint32_t o = sw_off(row, ch);
                uint32_t r4[4];
                ldsm4(r4, base + 16384 + o);
                bhi[2 * p][0] = r4[0]; bhi[2 * p][1] = r4[1];
                bhi[2 * p + 1][0] = r4[2]; bhi[2 * p + 1][1] = r4[3];
                ldsm4(r4, base + 24576 + o);
                blo[2 * p][0] = r4[0]; blo[2 * p][1] = r4[1];
                blo[2 * p + 1][0] = r4[2]; blo[2 * p + 1][1] = r4[3];
            }
#pragma unroll
            for (int mt = 0; mt < 4; mt++)
#pragma unroll
                for (int nt = 0; nt < 4; nt++) {
                    mma_f16(acc[mt][nt], ahi[mt], bhi[nt]);
                    mma_f16(acc[mt][nt], ahi[mt], blo[nt]);
                    mma_f16(acc[mt][nt], alo[mt], bhi[nt]);
                }
        }
        __syncthreads();
        stage ^= 1;
    }
    const int g = lane >> 2, tig = lane & 3;
    const int bofs = biasPerBatch ? b * M : 0;
#pragma unroll
    for (int mt = 0; mt < 4; mt++) {
        int r0 = m0 + wm + mt * 16 + g;
        float b0v = bias[bofs + r0];
        float b1v = bias[bofs + r0 + 8];
        float* orow0 = O + ((size_t)b * M + r0) * S + n0;
        float* orow1 = orow0 + (size_t)8 * S;
#pragma unroll
        for (int nt = 0; nt < 4; nt++) {
            int col = wn + nt * 8 + 2 * tig;
            *reinterpret_cast<float2*>(orow0 + col) =
                make_float2(acc[mt][nt][0] + b0v, acc[mt][nt][1] + b0v);
            *reinterpret_cast<float2*>(orow1 + col) =
                make_float2(acc[mt][nt][2] + b1v, acc[mt][nt][3] + b1v);
        }
    }
}

// ---------------- kernel 6: centers (pooled pipeline -> cns, vcs) ----------------
__global__ __launch_bounds__(256)
void centers_kernel(const float* __restrict__ w1, const float* __restrict__ bb1,
                    const float* __restrict__ w2, const float* __restrict__ bb2) {
    const int tid = threadIdx.x;
    const int bbk = blockIdx.x;           // b*32 + h*4 + win
    const int b = bbk >> 5;
    const int h = (bbk >> 2) & 7;
    const int fi = (bbk >> 1) & 1;
    const int fj = bbk & 1;

    __shared__ float a8[2048];
    __shared__ float hbuf[HIDM * 64];
    __shared__ float w1s[HIDM * HDIM], b1s[HIDM], w2s[HDIM * HIDM], b2s[HDIM];
    __shared__ float ctrs[128], vcs[128], cavg[128];
    __shared__ float cnorm[4];

    for (int i = tid; i < HIDM * HDIM; i += 256) { w1s[i] = w1[i]; w2s[i] = w2[i]; }
    if (tid < HIDM) b1s[tid] = bb1[tid];
    if (tid < HDIM) b2s[tid] = bb2[tid];

    for (int pass = 0; pass < 2; pass++) {
        const int base_row = (pass == 0) ? (256 + h * HDIM) : (h * HDIM);
        float* dst = (pass == 0) ? vcs : ctrs;
        __syncthreads();
#pragma unroll
        for (int rep = 0; rep < 8; rep++) {
            int e = rep * 256 + tid;
            int c = e >> 6, pos = e & 63;
            a8[c * 64 + pos] = g_pxv[((size_t)(b * 512) + base_row + c) * 256
                                     + (fi * 8 + (pos >> 3)) * 16 + fj * 8 + (pos & 7)];
        }
        __syncthreads();
        if (tid < 128) {
            int m = tid >> 5, c = tid & 31, qi = m >> 1, qj = m & 1;
            float s = 0.f;
#pragma unroll
            for (int u = 0; u < 4; u++)
#pragma unroll
                for (int v2 = 0; v2 < 4; v2++)
                    s += a8[c * 64 + (qi * 4 + u) * 8 + qj * 4 + v2];
            cavg[tid] = s * (1.f / 16.f);
        }
        for (int eh = tid; eh < HIDM * 64; eh += 256) {
            int j = eh >> 6, p = eh & 63;
            float s = b1s[j];
#pragma unroll
            for (int c = 0; c < HDIM; c++) s += w1s[j * HDIM + c] * a8[c * 64 + p];
            hbuf[eh] = 0.5f * s * (1.f + erff(s * 0.70710678118654752440f));
        }
        __syncthreads();
        for (int eo = tid; eo < 2048; eo += 256) {
            int c = eo >> 6, p = eo & 63;
            float s = b2s[c];
#pragma unroll
            for (int j = 0; j < HIDM; j++) s += w2s[c * HIDM + j] * hbuf[j * 64 + p];
            a8[eo] = s;
        }
        __syncthreads();
        if (tid < 128) {
            int m = tid >> 5, c = tid & 31, qi = m >> 1, qj = m & 1;
            float mx = -INFINITY;
#pragma unroll
            for (int u = 0; u < 4; u++)
#pragma unroll
                for (int v2 = 0; v2 < 4; v2++)
                    mx = fmaxf(mx, a8[c * 64 + (qi * 4 + u) * 8 + qj * 4 + v2]);
            dst[tid] = cavg[tid] + mx;
        }
        __syncthreads();
    }

    if (tid < 4) {
        float s = 0.f;
#pragma unroll
        for (int c = 0; c < HDIM; c++) { float v = ctrs[tid * 32 + c]; s += v * v; }
        cnorm[tid] = fmaxf(sqrtf(s), 1e-12f);
    }
    __syncthreads();
    if (tid < 128) {
        g_cns[(size_t)bbk * 128 + tid] = ctrs[tid] / cnorm[tid >> 5];
        g_vcs[(size_t)bbk * 128 + tid] = vcs[tid];
    }
}

// ---------------- kernel 7: main fused GEMM (fc1 only) + sim/argmax epilogue ----------------
__global__ __launch_bounds__(256, 2)
void gemm_sim_kernel(const __half* __restrict__ whi, const __half* __restrict__ wlo,
                     const __half* __restrict__ xhi, const __half* __restrict__ xlo,
                     const float* __restrict__ alphaP, const float* __restrict__ betaP) {
    extern __shared__ __align__(1024) char sm[];   // mainloop 64KB; epilogue 128x132 fp32
    __shared__ float cns_s[4][2][4][32];
    const int tid = threadIdx.x, lane = tid & 31, warp = tid >> 5;
    const int b = blockIdx.z, n0 = blockIdx.x * 128, m0 = blockIdx.y * 128;
    const int wm = (warp >> 2) * 64, wn = (warp & 3) * 32;

    const __half* srcs[4] = {
        whi + (size_t)m0 * DIMC, wlo + (size_t)m0 * DIMC,
        xhi + ((size_t)b * SPAT + n0) * DIMC, xlo + ((size_t)b * SPAT + n0) * DIMC };
    const uint32_t smb = smem_u32(sm);

    float acc[4][4][4];
#pragma unroll
    for (int i = 0; i < 4; i++)
#pragma unroll
        for (int j = 0; j < 4; j++)
#pragma unroll
            for (int k = 0; k < 4; k++) acc[i][j][k] = 0.f;

    auto load_stage = [&](int stage, int kc) {
#pragma unroll
        for (int t = 0; t < 4; t++) {
#pragma unroll
            for (int i = 0; i < 2; i++) {
                int chunkid = tid + 256 * i;
                int row = chunkid >> 2, c = chunkid & 3;
                cp_async16(smb + stage * 32768 + t * 8192 + sw_off(row, c),
                           srcs[t] + (size_t)row * DIMC + kc * 32 + c * 8);
            }
        }
        CP_COMMIT();
    };
    const int rl = lane & 7, sel = lane >> 3;

    load_stage(0, 0);
    int stage = 0;
    for (int kc = 0; kc < 8; kc++) {
        if (kc + 1 < 8) { load_stage(stage ^ 1, kc + 1); CP_WAIT(1); }
        else            { CP_WAIT(0); }
        __syncthreads();
        const uint32_t base = smb + stage * 32768;
#pragma unroll
        for (int ks = 0; ks < 2; ks++) {
            uint32_t ahi[4][4], alo[4][4];
#pragma unroll
            for (int mt = 0; mt < 4; mt++) {
                int row = wm + mt * 16 + (sel & 1) * 8 + rl;
                int ch = ks * 2 + (sel >> 1);
                uint32_t o = sw_off(row, ch);
                ldsm4(ahi[mt], base + o);
                ldsm4(alo[mt], base + 8192 + o);
            }
            uint32_t bhi[4][2], blo[4][2];
#pragma unroll
            for (int p = 0; p < 2; p++) {
                int row = wn + p * 16 + (sel >> 1) * 8 + rl;
                int ch = ks * 2 + (sel & 1);
                uint32_t o = sw_off(row, ch);
                uint32_t r4[4];
                ldsm4(r4, base + 16384 + o);
                bhi[2 * p][0] = r4[0]; bhi[2 * p][1] = r4[1];
                bhi[2 * p + 1][0] = r4[2]; bhi[2 * p + 1][1] = r4[3];
                ldsm4(r4, base + 24576 + o);
                blo[2 * p][0] = r4[0]; blo[2 * p][1] = r4[1];
                blo[2 * p + 1][0] = r4[2]; blo[2 * p + 1][1] = r4[3];
            }
#pragma unroll
            for (int mt = 0; mt < 4; mt++)
#pragma unroll
                for (int nt = 0; nt < 4; nt++) {
                    mma_f16(acc[mt][nt], ahi[mt], bhi[nt]);
                    mma_f16(acc[mt][nt], ahi[mt], blo[nt]);
                    mma_f16(acc[mt][nt], alo[mt], bhi[nt]);
                }
        }
        __syncthreads();
        stage ^= 1;
    }

    // ---- epilogue: x1 tile -> smem, then per-token norms + sims + argmax ----
    const int h0 = m0 >> 5;                 // first head of this CTA (0 or 4)
    const int fi = (n0 >= 2048) ? 1 : 0;
    float* epi = (float*)sm;                // [128 rows][132 stride]
    {
        const int g = lane >> 2, tig = lane & 3;
#pragma unroll
        for (int mt = 0; mt < 4; mt++) {
            int lr0 = wm + mt * 16 + g;
            float b0v = g_bb[b * 512 + m0 + lr0];
            float b1v = g_bb[b * 512 + m0 + lr0 + 8];
#pragma unroll
            for (int nt = 0; nt < 4; nt++) {
                int col = wn + nt * 8 + 2 * tig;
                epi[lr0 * 132 + col]           = acc[mt][nt][0] + b0v;
                epi[lr0 * 132 + col + 1]       = acc[mt][nt][1] + b0v;
                epi[(lr0 + 8) * 132 + col]     = acc[mt][nt][2] + b1v;
                epi[(lr0 + 8) * 132 + col + 1] = acc[mt][nt][3] + b1v;
            }
        }
    }
    // load centers for this CTA's 4 heads x 2 windows
    for (int i = tid; i < 1024; i += 256) {
        int hl = i >> 8, fjj = (i >> 7) & 1, m = (i >> 5) & 3, d = i & 31;
        int bbk = b * 32 + (h0 + hl) * 4 + fi * 2 + fjj;
        cns_s[hl][fjj][m][d] = g_cns[(size_t)bbk * 128 + m * 32 + d];
    }
    __syncthreads();

    const float alpha = alphaP[0], beta = betaP[0];
    const int hl = tid >> 6, tp = tid & 63;
#pragma unroll
    for (int rep = 0; rep < 2; rep++) {
        int tk = tp * 2 + rep;
        int s = n0 + tk;
        int hj = s & 63, fj = hj >> 5;
        int nw = ((s >> 6) & 31) * 32 + (hj & 31);
        float nrm = 0.f, dm[4] = {0.f, 0.f, 0.f, 0.f};
#pragma unroll
        for (int d = 0; d < 32; d++) {
            float v = epi[(hl * 32 + d) * 132 + tk];
            nrm += v * v;
#pragma unroll
            for (int m = 0; m < 4; m++) dm[m] += cns_s[hl][fj][m][d] * v;
        }
        float inv = 1.f / fmaxf(sqrtf(nrm), 1e-12f);
        float best = -1.f; int bm = 0;
#pragma unroll
        for (int m = 0; m < 4; m++) {
            float sg = 1.f / (1.f + expf(-(beta + alpha * dm[m] * inv)));
            if (sg > best) { best = sg; bm = m; }
        }
        size_t idx = ((size_t)(b * 8 + h0 + hl) * 4 + fi * 2 + fj) * 1024 + nw;
        g_sim[idx] = best;
        g_mstar[idx] = (unsigned char)bm;
    }
}

// ---------------- kernel 8: t = sum sim*x  (grid: 4 cgroups x 4 win x B) ----------------
__global__ __launch_bounds__(256)
void taccum_kernel() {
    const int cg = blockIdx.x;            // 0..3 -> channels cg*64..cg*64+64
    const int win = blockIdx.y;           // 0..3
    const int b = blockIdx.z;
    const int fi = win >> 1, fj = win & 1;
    const int tid = threadIdx.x;
    const int cp = tid & 31;              // channel pair: c = cg*64 + 2*cp
    const int h = tid >> 5;               // head 0..7

    __shared__ float stage[64][64];       // [t][c] fp32 reconstructed, 16KB
    __shared__ float ws[8][4][64];        // masked sims, 8KB

    float2 acc[4];
#pragma unroll
    for (int m = 0; m < 4; m++) acc[m] = make_float2(0.f, 0.f);

    for (int chunk = 0; chunk < 16; chunk++) {
        // stage 64 tokens x 64 channels: vectorized half2 loads (128B/warp) + float2 STS
#pragma unroll
        for (int it = 0; it < 8; it++) {
            int i = it * 256 + tid;       // 2048 half2 elements
            int t = i >> 5, cq = i & 31;
            int n = chunk * 64 + t;
            int s = (fi * 32 + (n >> 5)) * 64 + fj * 32 + (n & 31);
            size_t off2 = (((size_t)b * SPAT + s) * DIMC + cg * 64) / 2 + cq;
            float2 hf = __half22float2(reinterpret_cast<const __half2*>(g_xthi)[off2]);
            float2 lf = __half22float2(reinterpret_cast<const __half2*>(g_xtlo)[off2]);
            *reinterpret_cast<float2*>(&stage[t][2 * cq]) =
                make_float2(hf.x + lf.x, hf.y + lf.y);
        }
        // masked sims for this chunk
#pragma unroll
        for (int it = 0; it < 8; it++) {
            int i = it * 256 + tid;           // 8*4*64 = 2048 entries
            int hh = i >> 8, mm = (i >> 6) & 3, t = i & 63;
            size_t sb = ((size_t)(b * 8 + hh) * 4 + win) * 1024 + chunk * 64 + t;
            ws[hh][mm][t] = (g_mstar[sb] == (unsigned char)mm) ? g_sim[sb] : 0.f;
        }
        __syncthreads();
#pragma unroll 4
        for (int t = 0; t < 64; t++) {
            float2 xv = *reinterpret_cast<const float2*>(&stage[t][2 * cp]);
#pragma unroll
            for (int m = 0; m < 4; m++) {
                float w = ws[h][m][t];
                acc[m].x += w * xv.x;
                acc[m].y += w * xv.y;
            }
        }
        __syncthreads();
    }
#pragma unroll
    for (int m = 0; m < 4; m++) {
        size_t o = (((size_t)(b * 4 + win) * 8 + h) * 4 + m) * 256 + cg * 64 + 2 * cp;
        *reinterpret_cast<float2*>(&g_t[o]) = acc[m];
    }
}

// ---------------- kernel 9: outm + y fused (grid B*32 = (b,h,win)) ----------------
__global__ __launch_bounds__(256)
void outm_y_kernel(const float* __restrict__ wv, const float* __restrict__ w2) {
    const int bbk = blockIdx.x;           // b*32 + h*4 + win
    const int b = bbk >> 5;
    const int h = (bbk >> 2) & 7;
    const int win = bbk & 3;
    const int tid = threadIdx.x, lane = tid & 31, warp = tid >> 5;

    __shared__ float t_s[4][256];         // 4KB
    __shared__ float wbuf[8448];          // 33KB flat; Wv view [d*257+c], W2 view [o*33+d]
    __shared__ float sigs[4], cnts[4];
    __shared__ float outm_s[128];

    for (int i = tid; i < 1024; i += 256)
        t_s[i >> 8][i & 255] = g_t[(((size_t)(b * 4 + win) * 8 + h) * 4 + (i >> 8)) * 256 + (i & 255)];
    if (warp < 4) {
        float s = 0.f, c = 0.f;
        for (int n = lane; n < 1024; n += 32) {
            size_t sb = ((size_t)(b * 8 + h) * 4 + win) * 1024 + n;
            if (g_mstar[sb] == (unsigned char)warp) { s += g_sim[sb]; c += 1.f; }
        }
        for (int o = 16; o; o >>= 1) {
            s += __shfl_down_sync(0xffffffffu, s, o);
            c += __shfl_down_sync(0xffffffffu, c, o);
        }
        if (lane == 0) { sigs[warp] = s; cnts[warp] = c; }
    }
    for (int i = tid; i < 32 * 256; i += 256) {
        int r = i >> 8, c = i & 255;
        wbuf[r * 257 + c] = wv[(size_t)(h * HDIM + r) * DIMC + c];
    }
    __syncthreads();

    if (tid < 128) {
        int m = tid >> 5, d = tid & 31;
        float s = 0.f;
#pragma unroll 8
        for (int c = 0; c < DIMC; c++) s += wbuf[d * 257 + c] * t_s[m][c];
        float bbv = g_bb[b * 512 + 256 + h * HDIM + d];
        float vc = g_vcs[(size_t)bbk * 128 + m * 32 + d];
        outm_s[tid] = (s + sigs[m] * bbv + vc) / (cnts[m] + 1.f);
    }
    __syncthreads();
    for (int i = tid; i < 256 * 32; i += 256) {
        int o = i >> 5, d = i & 31;
        wbuf[o * 33 + d] = w2[(size_t)o * DIMC + h * HDIM + d];
    }
    __syncthreads();
    {
        int o = tid;
        float yv[4] = {0.f, 0.f, 0.f, 0.f};
#pragma unroll
        for (int d = 0; d < HDIM; d++) {
            float w = wbuf[o * 33 + d];
#pragma unroll
            for (int m = 0; m < 4; m++) yv[m] += w * outm_s[m * 32 + d];
        }
#pragma unroll
        for (int m = 0; m < 4; m++)
            g_y[(size_t)bbk * 1024 + m * 256 + o] = yv[m];
    }
}

// ---------------- kernel 10: combine -> final output ----------------
__global__ __launch_bounds__(256)
void combine_kernel(const float* __restrict__ b2, float* __restrict__ out) {
    const int o0 = blockIdx.x * 32;
    const int win = blockIdx.y;
    const int batch = blockIdx.z;
    const int fi = win >> 1, fj = win & 1;
    const int tid = threadIdx.x, lane = tid & 31, warp = tid >> 5;

    __shared__ float ys[8][4][33];
    __shared__ float b2s[32];

    for (int i = tid; i < 8 * 4 * 32; i += 256) {
        int h = i >> 7, m = (i >> 5) & 3, o = i & 31;
        ys[h][m][o] = g_y[((size_t)(batch * 8 + h) * 4 + win) * 1024 + m * 256 + o0 + o];
    }
    if (tid < 32) b2s[tid] = b2[o0 + tid];
    __syncthreads();

#pragma unroll
    for (int r = 0; r < 4; r++) {
        int wi = warp * 4 + r;
        int n = wi * 32 + lane;
        float simr[8];
        int mr[8];
#pragma unroll
        for (int h = 0; h < 8; h++) {
            size_t sb = ((size_t)(batch * 8 + h) * 4 + win) * 1024 + n;
            simr[h] = g_sim[sb];
            mr[h] = g_mstar[sb];
        }
        int s = (fi * 32 + wi) * 64 + fj * 32 + lane;
        float* op = out + ((size_t)batch * DIMC + o0) * SPAT + s;
#pragma unroll
        for (int o = 0; o < 32; o++) {
            float acc = b2s[o];
#pragma unroll
            for (int h = 0; h < 8; h++) acc += simr[h] * ys[h][mr[h]][o];
            op[(size_t)o * SPAT] = acc;
        }
    }
}

// ---------------- launcher ----------------
extern "C" void kernel_launch(void* const* d_in, const int* in_sizes, int n_in,
                              void* d_out, int out_size) {
    const float* x      = (const float*)d_in[0];
    const float* scaler = (const float*)d_in[1];
    const float* w_fc1  = (const float*)d_in[2];
    const float* b_fc1  = (const float*)d_in[3];
    const float* w_fcv  = (const float*)d_in[4];
    const float* b_fcv  = (const float*)d_in[5];
    const float* w_fc2  = (const float*)d_in[6];
    const float* b_fc2  = (const float*)d_in[7];
    const float* alpha  = (const float*)d_in[8];
    const float* beta   = (const float*)d_in[9];
    const float* off_w1 = (const float*)d_in[10];
    const float* off_b1 = (const float*)d_in[11];
    const float* off_w2 = (const float*)d_in[12];
    const float* off_b2 = (const float*)d_in[13];
    float* out = (float*)d_out;

    int B = in_sizes[0] / (DIMC * SPAT);
    if (B > MAXB) B = MAXB;

    float *p_pool, *p_bb, *p_pxv;
    __half *p_w1h, *p_w1l, *p_xth, *p_xtl, *p_pth, *p_ptl;
    cudaGetSymbolAddress((void**)&p_pool, g_pool);
    cudaGetSymbolAddress((void**)&p_bb,   g_bb);
    cudaGetSymbolAddress((void**)&p_pxv,  g_pxv);
    cudaGetSymbolAddress((void**)&p_w1h,  g_w1hi);
    cudaGetSymbolAddress((void**)&p_w1l,  g_w1lo);
    cudaGetSymbolAddress((void**)&p_xth,  g_xthi);
    cudaGetSymbolAddress((void**)&p_xtl,  g_xtlo);
    cudaGetSymbolAddress((void**)&p_pth,  g_pthi);
    cudaGetSymbolAddress((void**)&p_ptl,  g_ptlo);

    static bool attr_set = false;
    if (!attr_set) {
        cudaFuncSetAttribute(gemm_hmma_kernel, cudaFuncAttributeMaxDynamicSharedMemorySize, 65536);
        cudaFuncSetAttribute(gemm_sim_kernel,  cudaFuncAttributeMaxDynamicSharedMemorySize, 67584);
        attr_set = true;
    }

    // 1. pooled x (16x16) + spatial mean, then adjusted biases
    pool_kernel<<<B * DIMC, 256>>>(x);
    bias_kernel<<<(B * 512 + 255) / 256, 256>>>(w_fc1, b_fc1, w_fcv, b_fcv, scaler, B);
    // 2. fp16 weight split, x transpose+split, pooled transpose+split
    convw_kernel<<<512, 256>>>(w_fc1, w_fcv);
    {
        dim3 g(SPAT / 32, DIMC / 32, B);
        convx_kernel<<<g, dim3(32, 8)>>>(x, p_xth, p_xtl, SPAT);
    }
    {
        dim3 g(256 / 32, DIMC / 32, B);
        convx_kernel<<<g, dim3(32, 8)>>>(p_pool, p_pth, p_ptl, 256);
    }
    // 3. pooled conv (fc1+fcv on pooled x)
    {
        dim3 grid(256 / 128, 512 / 128, B);
        gemm_hmma_kernel<<<grid, 256, 65536>>>(p_w1h, p_w1l, p_pth, p_ptl, p_bb, p_pxv, 512, 256, 1);
    }
    // 4. centers + normalized cn + value centers (tiny, pooled-only)
    centers_kernel<<<B * 32, 256>>>(off_w1, off_b1, off_w2, off_b2);
    // 5. main fused GEMM: fc1(x) + per-token norm/sim/argmax (no x1 materialization)
    {
        dim3 grid(SPAT / 128, 256 / 128, B);
        gemm_sim_kernel<<<grid, 256, 67584>>>(p_w1h, p_w1l, p_xth, p_xtl, alpha, beta);
    }
    // 6. t = sum sim*x per cluster (well-parallelized: 16*B blocks)
    {
        dim3 grid(4, 4, B);
        taccum_kernel<<<grid, 256>>>();
    }
    // 7. outm + y fused
    outm_y_kernel<<<B * 32, 256>>>(w_fcv, w_fc2);
    // 8. combine -> final output
    {
        dim3 grid(8, 4, B);
        combine_kernel<<<grid, 256>>>(b_fc2, out);
    }
}

// round 12
// speedup vs baseline: 1.9136x; 1.0492x over previous
#include <cuda_runtime.h>
#include <cuda_fp16.h>
#include <cstdint>
#include <math.h>

// ---------------- problem constants ----------------
#define DIMC   256
#define SPAT   4096
#define NHEAD  8
#define HDIM   32
#define HIDM   53
#define MAXB   16

// ---------------- device scratch ----------------
__device__ float g_mean[MAXB * DIMC];
__device__ float g_bb[MAXB * 512];                         // adjusted bias [fc1;fcv]
__device__ float g_pool[MAXB * DIMC * 256];                // 16x16 pooled x (avg 4x4)
__device__ __half g_w1hi[512 * DIMC], g_w1lo[512 * DIMC];  // [fc1;fcv] fp16 split
__device__ __half g_xthi[(size_t)MAXB * SPAT * DIMC];      // X^T [b][s][k] fp16 split
__device__ __half g_xtlo[(size_t)MAXB * SPAT * DIMC];
__device__ __half g_pthi[MAXB * 256 * DIMC];               // pooled^T [b][p][k]
__device__ __half g_ptlo[MAXB * 256 * DIMC];
__device__ float g_pxv[MAXB * 512 * 256];                  // pooled fc1+fcv out
__device__ float g_cns[512 * 128];                         // normalized centers
__device__ float g_vcs[512 * 128];                         // value centers
__device__ float g_sim[(size_t)MAXB * 32 * 1024];          // per-(b,h,win) token sim
__device__ unsigned char g_mstar[(size_t)MAXB * 32 * 1024];
__device__ float g_t[(size_t)MAXB * 4 * 8 * 4 * 256];      // [b][win][h][m][c]
__device__ float g_y[512 * 1024];                          // W2 . outm

// ---------------- PTX helpers ----------------
__device__ __forceinline__ uint32_t smem_u32(const void* p) {
    uint32_t a;
    asm("{ .reg .u64 t; cvta.to.shared.u64 t, %1; cvt.u32.u64 %0, t; }" : "=r"(a) : "l"(p));
    return a;
}
__device__ __forceinline__ void cp_async16(uint32_t s, const void* g) {
    asm volatile("cp.async.cg.shared.global [%0], [%1], 16;" :: "r"(s), "l"(g));
}
#define CP_COMMIT() asm volatile("cp.async.commit_group;" ::: "memory")
#define CP_WAIT(n)  asm volatile("cp.async.wait_group %0;" :: "n"(n) : "memory")

__device__ __forceinline__ void ldsm4(uint32_t* r, uint32_t a) {
    asm volatile("ldmatrix.sync.aligned.m8n8.x4.shared.b16 {%0,%1,%2,%3}, [%4];"
        : "=r"(r[0]), "=r"(r[1]), "=r"(r[2]), "=r"(r[3]) : "r"(a));
}
__device__ __forceinline__ void mma_f16(float* d, const uint32_t* a, const uint32_t* b) {
    asm volatile("mma.sync.aligned.m16n8k16.row.col.f32.f16.f16.f32 "
        "{%0,%1,%2,%3}, {%4,%5,%6,%7}, {%8,%9}, {%0,%1,%2,%3};"
        : "+f"(d[0]), "+f"(d[1]), "+f"(d[2]), "+f"(d[3])
        : "r"(a[0]), "r"(a[1]), "r"(a[2]), "r"(a[3]), "r"(b[0]), "r"(b[1]));
}
__device__ __forceinline__ void hsplit(float v, __half& h, __half& l) {
    h = __float2half_rn(v);
    l = __float2half_rn(v - __half2float(h));
}
// smem tile: 128 rows x 32 f16 (64B/row), 16B-chunk XOR swizzle
__device__ __forceinline__ uint32_t sw_off(int row, int chunk) {
    return (uint32_t)(row * 64 + ((chunk ^ ((row >> 1) & 3)) << 4));
}

// ---------------- kernel 1: fused x reader: transpose+split AND 4x4 pool ----------------
// Block covers 4 rows x 64 cols x 32 channels. Grid (16 rowgroups, 8 cgroups, B).
__global__ __launch_bounds__(256)
void convxp_kernel(const float* __restrict__ x) {
    __shared__ float sbuf[32][257];       // [ci][r*64+col], padded
    const int rg = blockIdx.x;            // 0..15
    const int cgp = blockIdx.y;           // 0..7
    const int b = blockIdx.z;
    const int tid = threadIdx.x;

    // load: 32 channels x 256 consecutive s (rows rg*4..rg*4+3)
#pragma unroll
    for (int ci = 0; ci < 32; ci++)
        sbuf[ci][tid] = x[((size_t)(b * DIMC + cgp * 32 + ci)) * SPAT + rg * 256 + tid];
    __syncthreads();

    // transpose + fp16 split: thread tid = local s; write 32 channels (64B) vectorized
    {
        int s = rg * 256 + tid;
        size_t o = ((size_t)b * SPAT + s) * DIMC + cgp * 32;
        __half hv[32], lv[32];
#pragma unroll
        for (int ci = 0; ci < 32; ci++)
            hsplit(sbuf[ci][tid], hv[ci], lv[ci]);
        uint4* ph = reinterpret_cast<uint4*>(g_xthi + o);
        uint4* pl = reinterpret_cast<uint4*>(g_xtlo + o);
#pragma unroll
        for (int q = 0; q < 4; q++) {
            ph[q] = *reinterpret_cast<uint4*>(&hv[q * 8]);
            pl[q] = *reinterpret_cast<uint4*>(&lv[q * 8]);
        }
    }
    // pool: one complete pool-row (4 rows) x 16 pool-cols x 32 ch
    {
        int ci = tid >> 3;
        int pc0 = (tid & 7) * 2;
#pragma unroll
        for (int dp = 0; dp < 2; dp++) {
            int pcol = pc0 + dp;
            float s = 0.f;
#pragma unroll
            for (int r = 0; r < 4; r++)
#pragma unroll
                for (int u = 0; u < 4; u++)
                    s += sbuf[ci][r * 64 + pcol * 4 + u];
            g_pool[((size_t)(b * DIMC + cgp * 32 + ci)) * 256 + rg * 16 + pcol] = s * (1.f / 16.f);
        }
    }
}

// ---------------- kernel 1b: mean from pooled (exact partition average) ----------------
__global__ __launch_bounds__(256)
void mean2_kernel() {
    int warp = threadIdx.x >> 5, lane = threadIdx.x & 31;
    int bc = blockIdx.x * 8 + warp;       // grid = B*32
    const float* p = g_pool + (size_t)bc * 256;
    float s = 0.f;
#pragma unroll
    for (int i = 0; i < 8; i++) s += p[lane + i * 32];
    for (int o = 16; o; o >>= 1) s += __shfl_down_sync(0xffffffffu, s, o);
    if (lane == 0) g_mean[bc] = s * (1.f / 256.f);
}

// ---------------- kernel 2: adjusted bias ----------------
__global__ void bias_kernel(const float* __restrict__ w1, const float* __restrict__ b1,
                            const float* __restrict__ wv, const float* __restrict__ bv,
                            const float* __restrict__ scaler, int B) {
    int id = blockIdx.x * blockDim.x + threadIdx.x;
    if (id >= B * 512) return;
    int b = id >> 9, r = id & 511;
    const float* w = (r < 256) ? (w1 + (size_t)r * DIMC) : (wv + (size_t)(r - 256) * DIMC);
    float base = (r < 256) ? b1[r] : bv[r - 256];
    const float* mn = g_mean + b * DIMC;
    float s = 0.f;
#pragma unroll 8
    for (int c = 0; c < DIMC; c++) s += w[c] * scaler[c] * mn[c];
    g_bb[id] = base + s;
}

// ---------------- kernel 3: weight fp16 split ([fc1;fcv]) ----------------
__global__ void convw_kernel(const float* __restrict__ w1, const float* __restrict__ wv) {
    int i = blockIdx.x * blockDim.x + threadIdx.x;
    if (i < 65536) hsplit(w1[i], g_w1hi[i], g_w1lo[i]);
    else if (i < 131072) hsplit(wv[i - 65536], g_w1hi[i], g_w1lo[i]);
}

// ---------------- kernel 4: transpose+split [b][c][S] -> [b][s][c] hi/lo (pooled) ----------------
__global__ void convx_kernel(const float* __restrict__ src, __half* __restrict__ dhi,
                             __half* __restrict__ dlo, int S) {
    __shared__ float t[32][33];
    int s0 = blockIdx.x * 32, c0 = blockIdx.y * 32, b = blockIdx.z;
    int tx = threadIdx.x, ty = threadIdx.y;
#pragma unroll
    for (int i = 0; i < 4; i++)
        t[ty + i * 8][tx] = src[((size_t)(b * DIMC + c0 + ty + i * 8)) * S + s0 + tx];
    __syncthreads();
#pragma unroll
    for (int i = 0; i < 4; i++) {
        int s = s0 + ty + i * 8;
        float v = t[tx][ty + i * 8];
        __half h, l;
        hsplit(v, h, l);
        size_t o = ((size_t)b * S + s) * DIMC + c0 + tx;
        dhi[o] = h;
        dlo[o] = l;
    }
}

// ---------------- kernel 5: generic HMMA fp16-split GEMM (pooled conv) ----------------
__global__ __launch_bounds__(256)
void gemm_hmma_kernel(const __half* __restrict__ whi, const __half* __restrict__ wlo,
                      const __half* __restrict__ xhi, const __half* __restrict__ xlo,
                      const float* __restrict__ bias, float* __restrict__ O,
                      int M, int S, int biasPerBatch) {
    extern __shared__ __align__(1024) char sm[];
    const int tid = threadIdx.x, lane = tid & 31, warp = tid >> 5;
    const int b = blockIdx.z, n0 = blockIdx.x * 128, m0 = blockIdx.y * 128;
    const int wm = (warp >> 2) * 64, wn = (warp & 3) * 32;

    const __half* srcs[4] = {
        whi + (size_t)m0 * DIMC, wlo + (size_t)m0 * DIMC,
        xhi + ((size_t)b * S + n0) * DIMC, xlo + ((size_t)b * S + n0) * DIMC };
    const uint32_t smb = smem_u32(sm);

    float acc[4][4][4];
#pragma unroll
    for (int i = 0; i < 4; i++)
#pragma unroll
        for (int j = 0; j < 4; j++)
#pragma unroll
            for (int k = 0; k < 4; k++) acc[i][j][k] = 0.f;

    auto load_stage = [&](int stage, int kc) {
#pragma unroll
        for (int t = 0; t < 4; t++) {
#pragma unroll
            for (int i = 0; i < 2; i++) {
                int chunkid = tid + 256 * i;
                int row = chunkid >> 2, c = chunkid & 3;
                cp_async16(smb + stage * 32768 + t * 8192 + sw_off(row, c),
                           srcs[t] + (size_t)row * DIMC + kc * 32 + c * 8);
            }
        }
        CP_COMMIT();
    };
    const int rl = lane & 7, sel = lane >> 3;

    load_stage(0, 0);
    int stage = 0;
    for (int kc = 0; kc < 8; kc++) {
        if (kc + 1 < 8) { load_stage(stage ^ 1, kc + 1); CP_WAIT(1); }
        else            { CP_WAIT(0); }
        __syncthreads();
        const uint32_t base = smb + stage * 32768;
#pragma unroll
        for (int ks = 0; ks < 2; ks++) {
            uint32_t ahi[4][4], alo[4][4];
#pragma unroll
            for (int mt = 0; mt < 4; mt++) {
                int row = wm + mt * 16 + (sel & 1) * 8 + rl;
                int ch = ks * 2 + (sel >> 1);
                uint32_t o = sw_off(row, ch);
                ldsm4(ahi[mt], base + o);
                ldsm4(alo[mt], base + 8192 + o);
            }
            uint32_t bhi[4][2], blo[4][2];
#pragma unroll
            for (int p = 0; p < 2; p++) {
                int row = wn + p * 16 + (sel >> 1) * 8 + rl;
                int ch = ks * 2 + (sel & 1);
                uint32_t o = sw_off(row, ch);
                uint32_t r4[4];
                ldsm4(r4, base + 16384 + o);
                bhi[2 * p][0] = r4[0]; bhi[2 * p][1] = r4[1];
                bhi[2 * p + 1][0] = r4[2]; bhi[2 * p + 1][1] = r4[3];
                ldsm4(r4, base + 24576 + o);
                blo[2 * p][0] = r4[0]; blo[2 * p][1] = r4[1];
                blo[2 * p + 1][0] = r4[2]; blo[2 * p + 1][1] = r4[3];
            }
#pragma unroll
            for (int mt = 0; mt < 4; mt++)
#pragma unroll
                for (int nt = 0; nt < 4; nt++) {
                    mma_f16(acc[mt][nt], ahi[mt], bhi[nt]);
                    mma_f16(acc[mt][nt], ahi[mt], blo[nt]);
                    mma_f16(acc[mt][nt], alo[mt], bhi[nt]);
                }
        }
        __syncthreads();
        stage ^= 1;
    }
    const int g = lane >> 2, tig = lane & 3;
    const int bofs = biasPerBatch ? b * M : 0;
#pragma unroll
    for (int mt = 0; mt < 4; mt++) {
        int r0 = m0 + wm + mt * 16 + g;
        float b0v = bias[bofs + r0];
        float b1v = bias[bofs + r0 + 8];
        float* orow0 = O + ((size_t)b * M + r0) * S + n0;
        float* orow1 = orow0 + (size_t)8 * S;
#pragma unroll
        for (int nt = 0; nt < 4; nt++) {
            int col = wn + nt * 8 + 2 * tig;
            *reinterpret_cast<float2*>(orow0 + col) =
                make_float2(acc[mt][nt][0] + b0v, acc[mt][nt][1] + b0v);
            *reinterpret_cast<float2*>(orow1 + col) =
                make_float2(acc[mt][nt][2] + b1v, acc[mt][nt][3] + b1v);
        }
    }
}

// ---------------- kernel 6: centers (pooled pipeline -> cns, vcs) ----------------
__global__ __launch_bounds__(256)
void centers_kernel(const float* __restrict__ w1, const float* __restrict__ bb1,
                    const float* __restrict__ w2, const float* __restrict__ bb2) {
    const int tid = threadIdx.x;
    const int bbk = blockIdx.x;           // b*32 + h*4 + win
    const int b = bbk >> 5;
    const int h = (bbk >> 2) & 7;
    const int fi = (bbk >> 1) & 1;
    const int fj = bbk & 1;

    __shared__ float a8[2048];
    __shared__ float hbuf[HIDM * 64];
    __shared__ float w1s[HIDM * HDIM], b1s[HIDM], w2s[HDIM * HIDM], b2s[HDIM];
    __shared__ float ctrs[128], vcs[128], cavg[128];
    __shared__ float cnorm[4];

    for (int i = tid; i < HIDM * HDIM; i += 256) { w1s[i] = w1[i]; w2s[i] = w2[i]; }
    if (tid < HIDM) b1s[tid] = bb1[tid];
    if (tid < HDIM) b2s[tid] = bb2[tid];

    for (int pass = 0; pass < 2; pass++) {
        const int base_row = (pass == 0) ? (256 + h * HDIM) : (h * HDIM);
        float* dst = (pass == 0) ? vcs : ctrs;
        __syncthreads();
#pragma unroll
        for (int rep = 0; rep < 8; rep++) {
            int e = rep * 256 + tid;
            int c = e >> 6, pos = e & 63;
            a8[c * 64 + pos] = g_pxv[((size_t)(b * 512) + base_row + c) * 256
                                     + (fi * 8 + (pos >> 3)) * 16 + fj * 8 + (pos & 7)];
        }
        __syncthreads();
        if (tid < 128) {
            int m = tid >> 5, c = tid & 31, qi = m >> 1, qj = m & 1;
            float s = 0.f;
#pragma unroll
            for (int u = 0; u < 4; u++)
#pragma unroll
                for (int v2 = 0; v2 < 4; v2++)
                    s += a8[c * 64 + (qi * 4 + u) * 8 + qj * 4 + v2];
            cavg[tid] = s * (1.f / 16.f);
        }
        for (int eh = tid; eh < HIDM * 64; eh += 256) {
            int j = eh >> 6, p = eh & 63;
            float s = b1s[j];
#pragma unroll
            for (int c = 0; c < HDIM; c++) s += w1s[j * HDIM + c] * a8[c * 64 + p];
            hbuf[eh] = 0.5f * s * (1.f + erff(s * 0.70710678118654752440f));
        }
        __syncthreads();
        for (int eo = tid; eo < 2048; eo += 256) {
            int c = eo >> 6, p = eo & 63;
            float s = b2s[c];
#pragma unroll
            for (int j = 0; j < HIDM; j++) s += w2s[c * HIDM + j] * hbuf[j * 64 + p];
            a8[eo] = s;
        }
        __syncthreads();
        if (tid < 128) {
            int m = tid >> 5, c = tid & 31, qi = m >> 1, qj = m & 1;
            float mx = -INFINITY;
#pragma unroll
            for (int u = 0; u < 4; u++)
#pragma unroll
                for (int v2 = 0; v2 < 4; v2++)
                    mx = fmaxf(mx, a8[c * 64 + (qi * 4 + u) * 8 + qj * 4 + v2]);
            dst[tid] = cavg[tid] + mx;
        }
        __syncthreads();
    }

    if (tid < 4) {
        float s = 0.f;
#pragma unroll
        for (int c = 0; c < HDIM; c++) { float v = ctrs[tid * 32 + c]; s += v * v; }
        cnorm[tid] = fmaxf(sqrtf(s), 1e-12f);
    }
    __syncthreads();
    if (tid < 128) {
        g_cns[(size_t)bbk * 128 + tid] = ctrs[tid] / cnorm[tid >> 5];
        g_vcs[(size_t)bbk * 128 + tid] = vcs[tid];
    }
}

// ---------------- kernel 7: main fused GEMM (fc1 only) + sim/argmax epilogue ----------------
// 3-stage cp.async pipeline (buffers kc%3), 2 CTAs/SM.
__global__ __launch_bounds__(256, 2)
void gemm_sim_kernel(const __half* __restrict__ whi, const __half* __restrict__ wlo,
                     const __half* __restrict__ xhi, const __half* __restrict__ xlo,
                     const float* __restrict__ alphaP, const float* __restrict__ betaP) {
    extern __shared__ __align__(1024) char sm[];   // 3 x 32KB stages; epilogue 128x132 fp32
    __shared__ float cns_s[4][2][4][32];
    const int tid = threadIdx.x, lane = tid & 31, warp = tid >> 5;
    const int b = blockIdx.z, n0 = blockIdx.x * 128, m0 = blockIdx.y * 128;
    const int wm = (warp >> 2) * 64, wn = (warp & 3) * 32;

    const __half* srcs[4] = {
        whi + (size_t)m0 * DIMC, wlo + (size_t)m0 * DIMC,
        xhi + ((size_t)b * SPAT + n0) * DIMC, xlo + ((size_t)b * SPAT + n0) * DIMC };
    const uint32_t smb = smem_u32(sm);

    float acc[4][4][4];
#pragma unroll
    for (int i = 0; i < 4; i++)
#pragma unroll
        for (int j = 0; j < 4; j++)
#pragma unroll
            for (int k = 0; k < 4; k++) acc[i][j][k] = 0.f;

    auto load_stage = [&](int stage, int kc) {
#pragma unroll
        for (int t = 0; t < 4; t++) {
#pragma unroll
            for (int i = 0; i < 2; i++) {
                int chunkid = tid + 256 * i;
                int row = chunkid >> 2, c = chunkid & 3;
                cp_async16(smb + stage * 32768 + t * 8192 + sw_off(row, c),
                           srcs[t] + (size_t)row * DIMC + kc * 32 + c * 8);
            }
        }
        CP_COMMIT();
    };
    const int rl = lane & 7, sel = lane >> 3;

    load_stage(0, 0);
    load_stage(1, 1);
    for (int kc = 0; kc < 8; kc++) {
        if (kc + 2 < 8)      { load_stage((kc + 2) % 3, kc + 2); CP_WAIT(2); }
        else if (kc + 1 < 8) { CP_WAIT(1); }
        else                 { CP_WAIT(0); }
        __syncthreads();
        const uint32_t base = smb + (kc % 3) * 32768;
#pragma unroll
        for (int ks = 0; ks < 2; ks++) {
            uint32_t ahi[4][4], alo[4][4];
#pragma unroll
            for (int mt = 0; mt < 4; mt++) {
                int row = wm + mt * 16 + (sel & 1) * 8 + rl;
                int ch = ks * 2 + (sel >> 1);
                uint32_t o = sw_off(row, ch);
                ldsm4(ahi[mt], base + o);
                ldsm4(alo[mt], base + 8192 + o);
            }
            uint32_t bhi[4][2], blo[4][2];
#pragma unroll
            for (int p = 0; p < 2; p++) {
                int row = wn + p * 16 + (sel >> 1) * 8 + rl;
                int ch = ks * 2 + (sel & 1);
                uint32_t o = sw_off(row, ch);
                uint32_t r4[4];
                ldsm4(r4, base + 16384 + o);
                bhi[2 * p][0] = r4[0]; bhi[2 * p][1] = r4[1];
                bhi[2 * p + 1][0] = r4[2]; bhi[2 * p + 1][1] = r4[3];
                ldsm4(r4, base + 24576 + o);
                blo[2 * p][0] = r4[0]; blo[2 * p][1] = r4[1];
                blo[2 * p + 1][0] = r4[2]; blo[2 * p + 1][1] = r4[3];
            }
#pragma unroll
            for (int mt = 0; mt < 4; mt++)
#pragma unroll
                for (int nt = 0; nt < 4; nt++) {
                    mma_f16(acc[mt][nt], ahi[mt], bhi[nt]);
                    mma_f16(acc[mt][nt], ahi[mt], blo[nt]);
                    mma_f16(acc[mt][nt], alo[mt], bhi[nt]);
                }
        }
        __syncthreads();
    }

    // ---- epilogue: x1 tile -> smem, then per-token norms + sims + argmax ----
    const int h0 = m0 >> 5;                 // first head of this CTA (0 or 4)
    const int fi = (n0 >= 2048) ? 1 : 0;
    float* epi = (float*)sm;                // [128 rows][132 stride]
    {
        const int g = lane >> 2, tig = lane & 3;
#pragma unroll
        for (int mt = 0; mt < 4; mt++) {
            int lr0 = wm + mt * 16 + g;
            float b0v = g_bb[b * 512 + m0 + lr0];
            float b1v = g_bb[b * 512 + m0 + lr0 + 8];
#pragma unroll
            for (int nt = 0; nt < 4; nt++) {
                int col = wn + nt * 8 + 2 * tig;
                epi[lr0 * 132 + col]           = acc[mt][nt][0] + b0v;
                epi[lr0 * 132 + col + 1]       = acc[mt][nt][1] + b0v;
                epi[(lr0 + 8) * 132 + col]     = acc[mt][nt][2] + b1v;
                epi[(lr0 + 8) * 132 + col + 1] = acc[mt][nt][3] + b1v;
            }
        }
    }
    // load centers for this CTA's 4 heads x 2 windows
    for (int i = tid; i < 1024; i += 256) {
        int hl = i >> 8, fjj = (i >> 7) & 1, m = (i >> 5) & 3, d = i & 31;
        int bbk = b * 32 + (h0 + hl) * 4 + fi * 2 + fjj;
        cns_s[hl][fjj][m][d] = g_cns[(size_t)bbk * 128 + m * 32 + d];
    }
    __syncthreads();

    const float alpha = alphaP[0], beta = betaP[0];
    const int hl = tid >> 6, tp = tid & 63;
#pragma unroll
    for (int rep = 0; rep < 2; rep++) {
        int tk = tp * 2 + rep;
        int s = n0 + tk;
        int hj = s & 63, fj = hj >> 5;
        int nw = ((s >> 6) & 31) * 32 + (hj & 31);
        float nrm = 0.f, dm[4] = {0.f, 0.f, 0.f, 0.f};
#pragma unroll
        for (int d = 0; d < 32; d++) {
            float v = epi[(hl * 32 + d) * 132 + tk];
            nrm += v * v;
#pragma unroll
            for (int m = 0; m < 4; m++) dm[m] += cns_s[hl][fj][m][d] * v;
        }
        float inv = 1.f / fmaxf(sqrtf(nrm), 1e-12f);
        float best = -1.f; int bm = 0;
#pragma unroll
        for (int m = 0; m < 4; m++) {
            float sg = 1.f / (1.f + expf(-(beta + alpha * dm[m] * inv)));
            if (sg > best) { best = sg; bm = m; }
        }
        size_t idx = ((size_t)(b * 8 + h0 + hl) * 4 + fi * 2 + fj) * 1024 + nw;
        g_sim[idx] = best;
        g_mstar[idx] = (unsigned char)bm;
    }
}

// ---------------- kernel 8: t = sum sim*x  (grid: 4 cgroups x 4 win x B) ----------------
__global__ __launch_bounds__(256)
void taccum_kernel() {
    const int cg = blockIdx.x;            // 0..3 -> channels cg*64..cg*64+64
    const int win = blockIdx.y;           // 0..3
    const int b = blockIdx.z;
    const int fi = win >> 1, fj = win & 1;
    const int tid = threadIdx.x;
    const int cp = tid & 31;              // channel pair: c = cg*64 + 2*cp
    const int h = tid >> 5;               // head 0..7

    __shared__ float stage[64][64];       // [t][c] fp32 reconstructed, 16KB
    __shared__ float ws[8][4][64];        // masked sims, 8KB

    float2 acc[4];
#pragma unroll
    for (int m = 0; m < 4; m++) acc[m] = make_float2(0.f, 0.f);

    for (int chunk = 0; chunk < 16; chunk++) {
#pragma unroll
        for (int it = 0; it < 8; it++) {
            int i = it * 256 + tid;       // 2048 half2 elements
            int t = i >> 5, cq = i & 31;
            int n = chunk * 64 + t;
            int s = (fi * 32 + (n >> 5)) * 64 + fj * 32 + (n & 31);
            size_t off2 = (((size_t)b * SPAT + s) * DIMC + cg * 64) / 2 + cq;
            float2 hf = __half22float2(reinterpret_cast<const __half2*>(g_xthi)[off2]);
            float2 lf = __half22float2(reinterpret_cast<const __half2*>(g_xtlo)[off2]);
            *reinterpret_cast<float2*>(&stage[t][2 * cq]) =
                make_float2(hf.x + lf.x, hf.y + lf.y);
        }
#pragma unroll
        for (int it = 0; it < 8; it++) {
            int i = it * 256 + tid;           // 8*4*64 = 2048 entries
            int hh = i >> 8, mm = (i >> 6) & 3, t = i & 63;
            size_t sb = ((size_t)(b * 8 + hh) * 4 + win) * 1024 + chunk * 64 + t;
            ws[hh][mm][t] = (g_mstar[sb] == (unsigned char)mm) ? g_sim[sb] : 0.f;
        }
        __syncthreads();
#pragma unroll 4
        for (int t = 0; t < 64; t++) {
            float2 xv = *reinterpret_cast<const float2*>(&stage[t][2 * cp]);
#pragma unroll
            for (int m = 0; m < 4; m++) {
                float w = ws[h][m][t];
                acc[m].x += w * xv.x;
                acc[m].y += w * xv.y;
            }
        }
        __syncthreads();
    }
#pragma unroll
    for (int m = 0; m < 4; m++) {
        size_t o = (((size_t)(b * 4 + win) * 8 + h) * 4 + m) * 256 + cg * 64 + 2 * cp;
        *reinterpret_cast<float2*>(&g_t[o]) = acc[m];
    }
}

// ---------------- kernel 9: outm + y fused (grid B*32 = (b,h,win)) ----------------
__global__ __launch_bounds__(256)
void outm_y_kernel(const float* __restrict__ wv, const float* __restrict__ w2) {
    const int bbk = blockIdx.x;           // b*32 + h*4 + win
    const int b = bbk >> 5;
    const int h = (bbk >> 2) & 7;
    const int win = bbk & 3;
    const int tid = threadIdx.x, lane = tid & 31, warp = tid >> 5;

    __shared__ float t_s[4][256];         // 4KB
    __shared__ float wbuf[8448];          // 33KB flat; Wv view [d*257+c], W2 view [o*33+d]
    __shared__ float sigs[4], cnts[4];
    __shared__ float outm_s[128];

    for (int i = tid; i < 1024; i += 256)
        t_s[i >> 8][i & 255] = g_t[(((size_t)(b * 4 + win) * 8 + h) * 4 + (i >> 8)) * 256 + (i & 255)];
    if (warp < 4) {
        float s = 0.f, c = 0.f;
        for (int n = lane; n < 1024; n += 32) {
            size_t sb = ((size_t)(b * 8 + h) * 4 + win) * 1024 + n;
            if (g_mstar[sb] == (unsigned char)warp) { s += g_sim[sb]; c += 1.f; }
        }
        for (int o = 16; o; o >>= 1) {
            s += __shfl_down_sync(0xffffffffu, s, o);
            c += __shfl_down_sync(0xffffffffu, c, o);
        }
        if (lane == 0) { sigs[warp] = s; cnts[warp] = c; }
    }
    for (int i = tid; i < 32 * 256; i += 256) {
        int r = i >> 8, c = i & 255;
        wbuf[r * 257 + c] = wv[(size_t)(h * HDIM + r) * DIMC + c];
    }
    __syncthreads();

    if (tid < 128) {
        int m = tid >> 5, d = tid & 31;
        float s = 0.f;
#pragma unroll 8
        for (int c = 0; c < DIMC; c++) s += wbuf[d * 257 + c] * t_s[m][c];
        float bbv = g_bb[b * 512 + 256 + h * HDIM + d];
        float vc = g_vcs[(size_t)bbk * 128 + m * 32 + d];
        outm_s[tid] = (s + sigs[m] * bbv + vc) / (cnts[m] + 1.f);
    }
    __syncthreads();
    for (int i = tid; i < 256 * 32; i += 256) {
        int o = i >> 5, d = i & 31;
        wbuf[o * 33 + d] = w2[(size_t)o * DIMC + h * HDIM + d];
    }
    __syncthreads();
    {
        int o = tid;
        float yv[4] = {0.f, 0.f, 0.f, 0.f};
#pragma unroll
        for (int d = 0; d < HDIM; d++) {
            float w = wbuf[o * 33 + d];
#pragma unroll
            for (int m = 0; m < 4; m++) yv[m] += w * outm_s[m * 32 + d];
        }
#pragma unroll
        for (int m = 0; m < 4; m++)
            g_y[(size_t)bbk * 1024 + m * 256 + o] = yv[m];
    }
}

// ---------------- kernel 10: combine -> final output ----------------
__global__ __launch_bounds__(256)
void combine_kernel(const float* __restrict__ b2, float* __restrict__ out) {
    const int o0 = blockIdx.x * 32;
    const int win = blockIdx.y;
    const int batch = blockIdx.z;
    const int fi = win >> 1, fj = win & 1;
    const int tid = threadIdx.x, lane = tid & 31, warp = tid >> 5;

    __shared__ float ys[8][4][33];
    __shared__ float b2s[32];

    for (int i = tid; i < 8 * 4 * 32; i += 256) {
        int h = i >> 7, m = (i >> 5) & 3, o = i & 31;
        ys[h][m][o] = g_y[((size_t)(batch * 8 + h) * 4 + win) * 1024 + m * 256 + o0 + o];
    }
    if (tid < 32) b2s[tid] = b2[o0 + tid];
    __syncthreads();

#pragma unroll
    for (int r = 0; r < 4; r++) {
        int wi = warp * 4 + r;
        int n = wi * 32 + lane;
        float simr[8];
        int mr[8];
#pragma unroll
        for (int h = 0; h < 8; h++) {
            size_t sb = ((size_t)(batch * 8 + h) * 4 + win) * 1024 + n;
            simr[h] = g_sim[sb];
            mr[h] = g_mstar[sb];
        }
        int s = (fi * 32 + wi) * 64 + fj * 32 + lane;
        float* op = out + ((size_t)batch * DIMC + o0) * SPAT + s;
#pragma unroll
        for (int o = 0; o < 32; o++) {
            float acc = b2s[o];
#pragma unroll
            for (int h = 0; h < 8; h++) acc += simr[h] * ys[h][mr[h]][o];
            op[(size_t)o * SPAT] = acc;
        }
    }
}

// ---------------- launcher ----------------
extern "C" void kernel_launch(void* const* d_in, const int* in_sizes, int n_in,
                              void* d_out, int out_size) {
    const float* x      = (const float*)d_in[0];
    const float* scaler = (const float*)d_in[1];
    const float* w_fc1  = (const float*)d_in[2];
    const float* b_fc1  = (const float*)d_in[3];
    const float* w_fcv  = (const float*)d_in[4];
    const float* b_fcv  = (const float*)d_in[5];
    const float* w_fc2  = (const float*)d_in[6];
    const float* b_fc2  = (const float*)d_in[7];
    const float* alpha  = (const float*)d_in[8];
    const float* beta   = (const float*)d_in[9];
    const float* off_w1 = (const float*)d_in[10];
    const float* off_b1 = (const float*)d_in[11];
    const float* off_w2 = (const float*)d_in[12];
    const float* off_b2 = (const float*)d_in[13];
    float* out = (float*)d_out;

    int B = in_sizes[0] / (DIMC * SPAT);
    if (B > MAXB) B = MAXB;

    float *p_pool, *p_bb, *p_pxv;
    __half *p_w1h, *p_w1l, *p_xth, *p_xtl, *p_pth, *p_ptl;
    cudaGetSymbolAddress((void**)&p_pool, g_pool);
    cudaGetSymbolAddress((void**)&p_bb,   g_bb);
    cudaGetSymbolAddress((void**)&p_pxv,  g_pxv);
    cudaGetSymbolAddress((void**)&p_w1h,  g_w1hi);
    cudaGetSymbolAddress((void**)&p_w1l,  g_w1lo);
    cudaGetSymbolAddress((void**)&p_xth,  g_xthi);
    cudaGetSymbolAddress((void**)&p_xtl,  g_xtlo);
    cudaGetSymbolAddress((void**)&p_pth,  g_pthi);
    cudaGetSymbolAddress((void**)&p_ptl,  g_ptlo);

    static bool attr_set = false;
    if (!attr_set) {
        cudaFuncSetAttribute(gemm_hmma_kernel, cudaFuncAttributeMaxDynamicSharedMemorySize, 65536);
        cudaFuncSetAttribute(gemm_sim_kernel,  cudaFuncAttributeMaxDynamicSharedMemorySize, 98304);
        attr_set = true;
    }

    // 1. fused x reader: transpose+split + pooled (single 67MB pass over x)
    {
        dim3 g(16, 8, B);
        convxp_kernel<<<g, 256>>>(x);
    }
    mean2_kernel<<<B * 32, 256>>>();
    bias_kernel<<<(B * 512 + 255) / 256, 256>>>(w_fc1, b_fc1, w_fcv, b_fcv, scaler, B);
    // 2. fp16 weight split, pooled transpose+split
    convw_kernel<<<512, 256>>>(w_fc1, w_fcv);
    {
        dim3 g(256 / 32, DIMC / 32, B);
        convx_kernel<<<g, dim3(32, 8)>>>(p_pool, p_pth, p_ptl, 256);
    }
    // 3. pooled conv (fc1+fcv on pooled x)
    {
        dim3 grid(256 / 128, 512 / 128, B);
        gemm_hmma_kernel<<<grid, 256, 65536>>>(p_w1h, p_w1l, p_pth, p_ptl, p_bb, p_pxv, 512, 256, 1);
    }
    // 4. centers + normalized cn + value centers (tiny, pooled-only)
    centers_kernel<<<B * 32, 256>>>(off_w1, off_b1, off_w2, off_b2);
    // 5. main fused GEMM: fc1(x) + per-token norm/sim/argmax (3-stage pipeline)
    {
        dim3 grid(SPAT / 128, 256 / 128, B);
        gemm_sim_kernel<<<grid, 256, 98304>>>(p_w1h, p_w1l, p_xth, p_xtl, alpha, beta);
    }
    // 6. t = sum sim*x per cluster
    {
        dim3 grid(4, 4, B);
        taccum_kernel<<<grid, 256>>>();
    }
    // 7. outm + y fused
    outm_y_kernel<<<B * 32, 256>>>(w_fcv, w_fc2);
    // 8. combine -> final output
    {
        dim3 grid(8, 4, B);
        combine_kernel<<<grid, 256>>>(b_fc2, out);
    }
}